// round 10
// baseline (speedup 1.0000x reference)
#include <cuda_runtime.h>
#include <cuda_bf16.h>
#include <cstdint>

#define N_NODES 50000
#define MAX_E   800000
#define D_IN    128
#define D_HID   256
#define D_OUT   128

// ---------------- scratch (static device globals; no allocation) ----------------
__device__ float g_neigh1[(size_t)N_NODES * D_IN];
__device__ float g_u[(size_t)N_NODES * D_HID];     // x@W1s + b1
__device__ float g_h1[(size_t)N_NODES * D_HID];
__device__ float g_s2[(size_t)N_NODES * D_OUT];
__device__ float g_t2[(size_t)N_NODES * D_OUT];
__device__ float g_sA[N_NODES];
__device__ float g_sB[N_NODES];
__device__ int   g_cnt[N_NODES];
__device__ int   g_rowptr[N_NODES + 1];
__device__ int   g_cursor[N_NODES];
__device__ int   g_csr_src[MAX_E];

// pre-split bf16 weights, same (K,N) layout as the fp32 originals
__device__ __nv_bfloat16 g_w1s_h[D_IN * D_HID], g_w1s_l[D_IN * D_HID];
__device__ __nv_bfloat16 g_w1n_h[D_IN * D_HID], g_w1n_l[D_IN * D_HID];
__device__ __nv_bfloat16 g_w2s_h[D_HID * D_OUT], g_w2s_l[D_HID * D_OUT];
__device__ __nv_bfloat16 g_w2n_h[D_HID * D_OUT], g_w2n_l[D_HID * D_OUT];

// ---------------- helpers ----------------
__device__ __forceinline__ uint32_t smem_u32(const void* p) {
    uint32_t a;
    asm("{ .reg .u64 t; cvta.to.shared.u64 t, %1; cvt.u32.u64 %0, t; }" : "=r"(a) : "l"(p));
    return a;
}
__device__ __forceinline__ uint32_t bpack(__nv_bfloat16 a, __nv_bfloat16 b) {
    return (uint32_t)__bfloat16_as_ushort(a) | ((uint32_t)__bfloat16_as_ushort(b) << 16);
}
__device__ __forceinline__ void split4(float4 v, uint32_t* h, uint32_t* l) {
    __nv_bfloat16 hx = __float2bfloat16_rn(v.x);
    __nv_bfloat16 hy = __float2bfloat16_rn(v.y);
    __nv_bfloat16 hz = __float2bfloat16_rn(v.z);
    __nv_bfloat16 hw = __float2bfloat16_rn(v.w);
    h[0] = bpack(hx, hy);
    h[1] = bpack(hz, hw);
    __nv_bfloat16 lx = __float2bfloat16_rn(v.x - __bfloat162float(hx));
    __nv_bfloat16 ly = __float2bfloat16_rn(v.y - __bfloat162float(hy));
    __nv_bfloat16 lz = __float2bfloat16_rn(v.z - __bfloat162float(hz));
    __nv_bfloat16 lw = __float2bfloat16_rn(v.w - __bfloat162float(hw));
    l[0] = bpack(lx, ly);
    l[1] = bpack(lz, lw);
}

#define LDSM_X4(r0, r1, r2, r3, addr) \
    asm volatile("ldmatrix.sync.aligned.m8n8.x4.shared.b16 {%0,%1,%2,%3}, [%4];" \
                 : "=r"(r0), "=r"(r1), "=r"(r2), "=r"(r3) : "r"(addr))
#define LDSM_X4T(r0, r1, r2, r3, addr) \
    asm volatile("ldmatrix.sync.aligned.m8n8.x4.trans.shared.b16 {%0,%1,%2,%3}, [%4];" \
                 : "=r"(r0), "=r"(r1), "=r"(r2), "=r"(r3) : "r"(addr))
#define MMA_BF16(c, a, b) \
    asm volatile("mma.sync.aligned.m16n8k16.row.col.f32.bf16.bf16.f32 " \
                 "{%0,%1,%2,%3}, {%4,%5,%6,%7}, {%8,%9}, {%0,%1,%2,%3};" \
                 : "+f"((c)[0]), "+f"((c)[1]), "+f"((c)[2]), "+f"((c)[3]) \
                 : "r"((a)[0]), "r"((a)[1]), "r"((a)[2]), "r"((a)[3]), \
                   "r"((b)[0]), "r"((b)[1]))
#define CP_ASYNC16(saddr, gptr) \
    asm volatile("cp.async.cg.shared.global [%0], [%1], 16;" :: "r"(saddr), "l"(gptr))
#define CP_COMMIT() asm volatile("cp.async.commit_group;")
#define CP_WAIT(n)  asm volatile("cp.async.wait_group %0;" :: "n"(n))

// ---------------- CSR build ----------------
__global__ void k_hist(const int* __restrict__ dst, int E) {
    int e = blockIdx.x * blockDim.x + threadIdx.x;
    if (e < E) atomicAdd(&g_cnt[dst[e]], 1);
}
__global__ void k_scan() {
    const int T = 1024;
    const int C = (N_NODES + T - 1) / T;
    __shared__ int partial[T];
    int t = threadIdx.x;
    int base = t * C;
    int s = 0;
    for (int i = 0; i < C; i++) {
        int idx = base + i;
        if (idx < N_NODES) s += g_cnt[idx];
    }
    partial[t] = s;
    __syncthreads();
    for (int off = 1; off < T; off <<= 1) {
        int v = (t >= off) ? partial[t - off] : 0;
        __syncthreads();
        partial[t] += v;
        __syncthreads();
    }
    int run = partial[t] - s;
    for (int i = 0; i < C; i++) {
        int idx = base + i;
        if (idx < N_NODES) {
            g_rowptr[idx] = run;
            g_cursor[idx] = run;
            run += g_cnt[idx];
        }
    }
    if (t == 0) g_rowptr[N_NODES] = partial[T - 1];
}
__global__ void k_fill(const int* __restrict__ src, const int* __restrict__ dst, int E) {
    int e = blockIdx.x * blockDim.x + threadIdx.x;
    if (e < E) {
        int d = dst[e];
        int pos = atomicAdd(&g_cursor[d], 1);
        g_csr_src[pos] = src[e];
    }
}

// ---------------- layer-1 aggregation (unrolled x2) ----------------
__global__ void k_agg128(const float* __restrict__ feat, float* __restrict__ out) {
    int warps_per_blk = blockDim.x >> 5;
    int n = blockIdx.x * warps_per_blk + (threadIdx.x >> 5);
    if (n >= N_NODES) return;
    int lane = threadIdx.x & 31;
    int beg = g_rowptr[n], end = g_rowptr[n + 1];

    float4 acc0 = {0.f, 0.f, 0.f, 0.f};
    float4 acc1 = {0.f, 0.f, 0.f, 0.f};
    int j = beg;
    for (; j + 1 < end; j += 2) {
        int s0 = g_csr_src[j];
        int s1 = g_csr_src[j + 1];
        float4 v0 = __ldg(&((const float4*)(feat + (size_t)s0 * 128))[lane]);
        float4 v1 = __ldg(&((const float4*)(feat + (size_t)s1 * 128))[lane]);
        acc0.x += v0.x; acc0.y += v0.y; acc0.z += v0.z; acc0.w += v0.w;
        acc1.x += v1.x; acc1.y += v1.y; acc1.z += v1.z; acc1.w += v1.w;
    }
    if (j < end) {
        int s0 = g_csr_src[j];
        float4 v0 = __ldg(&((const float4*)(feat + (size_t)s0 * 128))[lane]);
        acc0.x += v0.x; acc0.y += v0.y; acc0.z += v0.z; acc0.w += v0.w;
    }
    acc0.x += acc1.x; acc0.y += acc1.y; acc0.z += acc1.z; acc0.w += acc1.w;
    int deg = end - beg;
    float inv = (deg > 0) ? 1.f / (float)deg : 0.f;
    float4 o = {acc0.x * inv, acc0.y * inv, acc0.z * inv, acc0.w * inv};
    ((float4*)(out + (size_t)n * 128))[lane] = o;
}

// ---------------- weight split + cnt zeroing, one launch ----------------
__global__ void k_wprep_all(
    const float* __restrict__ W1s, const float* __restrict__ W1n,
    const float* __restrict__ W2s, const float* __restrict__ W2n)
{
    int i = blockIdx.x * blockDim.x + threadIdx.x;
    if (i < N_NODES) g_cnt[i] = 0;
    if (i >= 4 * 32768) return;
    int a = i >> 15, r = i & 32767;
    const float* W = (a == 0) ? W1s : (a == 1) ? W1n : (a == 2) ? W2s : W2n;
    __nv_bfloat16* hi = (a == 0) ? g_w1s_h : (a == 1) ? g_w1n_h : (a == 2) ? g_w2s_h : g_w2n_h;
    __nv_bfloat16* lo = (a == 0) ? g_w1s_l : (a == 1) ? g_w1n_l : (a == 2) ? g_w2s_l : g_w2n_l;
    float w = W[r];
    __nv_bfloat16 h = __float2bfloat16_rn(w);
    hi[r] = h;
    lo[r] = __float2bfloat16_rn(w - __bfloat162float(h));
}

// ================= bf16x3 mma.sync GEMMs =================
// CTA tile 128(M) x 64(N), BK=32. 8 warps: wm=wid&3 (M), wn=wid>>2 (N).
// A tiles: 128 rows x 40 bf16 (80B rows), single-buffered, split-in-kernel from fp32.
// B tiles: 32 rows x 64 bf16, 128B XOR-swizzled rows, double-buffered cp.async.
#define A_TILE_B 10240
#define B_TILE_B 4096

// -------- single GEMM: U = A@B + bias (no activation) --------
template <bool ADDU, bool RELU>
__global__ void __launch_bounds__(256) k_mm_single(
    const float* __restrict__ A,
    const __nv_bfloat16* __restrict__ Bh, const __nv_bfloat16* __restrict__ Bl,
    const float* __restrict__ bias, const float* __restrict__ U,
    float* __restrict__ C, int M, int N, int K)
{
    extern __shared__ char smem[];
    const int OAH = 0, OAL = A_TILE_B;
    const int OB_BASE = 2 * A_TILE_B;      // 2 buffers x 2 tiles x 4096
    uint32_t sb = smem_u32(smem);

    int tid = threadIdx.x, lane = tid & 31, wid = tid >> 5;
    int wm = wid & 3, wn = wid >> 2;
    int bm = blockIdx.y * 128, bn = blockIdx.x * 64;
    const int nch = K >> 5;

    int brow = tid >> 3, bseg = tid & 7;
    uint32_t bso = (uint32_t)(brow * 128 + ((bseg ^ (brow & 7)) << 4));
    const __nv_bfloat16* gB[2] = {Bh, Bl};

    float acc[2][4][4];
#pragma unroll
    for (int i = 0; i < 2; i++)
#pragma unroll
        for (int j = 0; j < 4; j++)
#pragma unroll
            for (int q = 0; q < 4; q++) acc[i][j][q] = 0.f;

    {
        size_t ge = (size_t)brow * N + bn + bseg * 8;
#pragma unroll
        for (int t = 0; t < 2; t++)
            CP_ASYNC16(sb + OB_BASE + t * B_TILE_B + bso, gB[t] + ge);
        CP_COMMIT();
    }

    for (int chunk = 0; chunk < nch; chunk++) {
        int k0 = chunk << 5;
        int obuf = OB_BASE + (chunk & 1) * 2 * B_TILE_B;

        // stage A (split fp32 -> bf16 h/l)
#pragma unroll
        for (int q = 0; q < 4; q++) {
            int slot = tid + q * 256;
            int row = slot >> 3, k4 = (slot & 7) * 4;
            int gr = bm + row;
            float4 v = {0.f, 0.f, 0.f, 0.f};
            if (gr < M) v = *(const float4*)(A + (size_t)gr * K + k0 + k4);
            uint32_t h[2], l[2];
            split4(v, h, l);
            int si = row * 20 + (k4 >> 1);
            ((uint32_t*)(smem + OAH))[si] = h[0];
            ((uint32_t*)(smem + OAH))[si + 1] = h[1];
            ((uint32_t*)(smem + OAL))[si] = l[0];
            ((uint32_t*)(smem + OAL))[si + 1] = l[1];
        }

        if (chunk + 1 < nch) {
            int nbuf = OB_BASE + ((chunk + 1) & 1) * 2 * B_TILE_B;
            size_t ge = (size_t)(((chunk + 1) << 5) + brow) * N + bn + bseg * 8;
#pragma unroll
            for (int t = 0; t < 2; t++)
                CP_ASYNC16(sb + nbuf + t * B_TILE_B + bso, gB[t] + ge);
            CP_COMMIT();
            CP_WAIT(1);
        } else {
            CP_WAIT(0);
        }
        __syncthreads();

#pragma unroll
        for (int kk = 0; kk < 2; kk++) {
            uint32_t fah[2][4], fal[2][4];
#pragma unroll
            for (int mi = 0; mi < 2; mi++) {
                uint32_t aoff = (uint32_t)((wm * 32 + mi * 16 + (lane & 15)) * 80 +
                                           (lane >> 4) * 16 + kk * 32);
                LDSM_X4(fah[mi][0], fah[mi][1], fah[mi][2], fah[mi][3], sb + OAH + aoff);
                LDSM_X4(fal[mi][0], fal[mi][1], fal[mi][2], fal[mi][3], sb + OAL + aoff);
            }
            uint32_t fbh[4][2], fbl[4][2];
#pragma unroll
            for (int np = 0; np < 2; np++) {
                int r = kk * 16 + (lane & 7) + ((lane >> 3) & 1) * 8;
                int cu = wn * 4 + np * 2 + (lane >> 4);
                uint32_t boff = (uint32_t)(r * 128 + ((cu ^ (r & 7)) << 4));
                LDSM_X4T(fbh[2 * np][0], fbh[2 * np][1], fbh[2 * np + 1][0], fbh[2 * np + 1][1], sb + obuf + 0 * B_TILE_B + boff);
                LDSM_X4T(fbl[2 * np][0], fbl[2 * np][1], fbl[2 * np + 1][0], fbl[2 * np + 1][1], sb + obuf + 1 * B_TILE_B + boff);
            }
#pragma unroll
            for (int mi = 0; mi < 2; mi++)
#pragma unroll
                for (int nj = 0; nj < 4; nj++) {
                    MMA_BF16(acc[mi][nj], fah[mi], fbh[nj]);
                    MMA_BF16(acc[mi][nj], fah[mi], fbl[nj]);
                    MMA_BF16(acc[mi][nj], fal[mi], fbh[nj]);
                }
        }
        __syncthreads();
    }

    int g = lane >> 2, c2 = (lane & 3) * 2;
#pragma unroll
    for (int mi = 0; mi < 2; mi++)
#pragma unroll
        for (int nj = 0; nj < 4; nj++) {
            int col = bn + wn * 32 + nj * 8 + c2;
            float2 bv = {0.f, 0.f};
            if (!ADDU) bv = *(const float2*)(bias + col);
#pragma unroll
            for (int half = 0; half < 2; half++) {
                int r = bm + wm * 32 + mi * 16 + g + half * 8;
                if (r >= M) continue;
                float cx = acc[mi][nj][2 * half + 0] + bv.x;
                float cy = acc[mi][nj][2 * half + 1] + bv.y;
                if (ADDU) {
                    float2 uv = *(const float2*)(U + (size_t)r * N + col);
                    cx += uv.x; cy += uv.y;
                }
                if (RELU) { cx = fmaxf(cx, 0.f); cy = fmaxf(cy, 0.f); }
                float2 o = {cx, cy};
                *(float2*)(C + (size_t)r * N + col) = o;
            }
        }
}

// -------- layer 2: S = A@Bs + bias, T = A@Bt --------
__global__ void __launch_bounds__(256) k_mm_pair(
    const float* __restrict__ A,
    const __nv_bfloat16* __restrict__ Bsh, const __nv_bfloat16* __restrict__ Bsl,
    const __nv_bfloat16* __restrict__ Bth, const __nv_bfloat16* __restrict__ Btl,
    const float* __restrict__ bias, float* __restrict__ S, float* __restrict__ T,
    int M, int N, int K)
{
    extern __shared__ char smem[];
    const int OAH = 0, OAL = A_TILE_B;
    const int OB_BASE = 2 * A_TILE_B;
    uint32_t sb = smem_u32(smem);

    int tid = threadIdx.x, lane = tid & 31, wid = tid >> 5;
    int wm = wid & 3, wn = wid >> 2;
    int bm = blockIdx.y * 128, bn = blockIdx.x * 64;
    const int nch = K >> 5;

    int brow = tid >> 3, bseg = tid & 7;
    uint32_t bso = (uint32_t)(brow * 128 + ((bseg ^ (brow & 7)) << 4));
    const __nv_bfloat16* gB[4] = {Bsh, Bsl, Bth, Btl};

    float accS[2][4][4], accT[2][4][4];
#pragma unroll
    for (int i = 0; i < 2; i++)
#pragma unroll
        for (int j = 0; j < 4; j++)
#pragma unroll
            for (int q = 0; q < 4; q++) { accS[i][j][q] = 0.f; accT[i][j][q] = 0.f; }

    {
        size_t ge = (size_t)brow * N + bn + bseg * 8;
#pragma unroll
        for (int t = 0; t < 4; t++)
            CP_ASYNC16(sb + OB_BASE + t * B_TILE_B + bso, gB[t] + ge);
        CP_COMMIT();
    }

    for (int chunk = 0; chunk < nch; chunk++) {
        int k0 = chunk << 5;
        int obuf = OB_BASE + (chunk & 1) * 4 * B_TILE_B;

#pragma unroll
        for (int q = 0; q < 4; q++) {
            int slot = tid + q * 256;
            int row = slot >> 3, k4 = (slot & 7) * 4;
            int gr = bm + row;
            float4 v = {0.f, 0.f, 0.f, 0.f};
            if (gr < M) v = *(const float4*)(A + (size_t)gr * K + k0 + k4);
            uint32_t h[2], l[2];
            split4(v, h, l);
            int si = row * 20 + (k4 >> 1);
            ((uint32_t*)(smem + OAH))[si] = h[0];
            ((uint32_t*)(smem + OAH))[si + 1] = h[1];
            ((uint32_t*)(smem + OAL))[si] = l[0];
            ((uint32_t*)(smem + OAL))[si + 1] = l[1];
        }

        if (chunk + 1 < nch) {
            int nbuf = OB_BASE + ((chunk + 1) & 1) * 4 * B_TILE_B;
            size_t ge = (size_t)(((chunk + 1) << 5) + brow) * N + bn + bseg * 8;
#pragma unroll
            for (int t = 0; t < 4; t++)
                CP_ASYNC16(sb + nbuf + t * B_TILE_B + bso, gB[t] + ge);
            CP_COMMIT();
            CP_WAIT(1);
        } else {
            CP_WAIT(0);
        }
        __syncthreads();

#pragma unroll
        for (int kk = 0; kk < 2; kk++) {
            uint32_t fah[2][4], fal[2][4];
#pragma unroll
            for (int mi = 0; mi < 2; mi++) {
                uint32_t aoff = (uint32_t)((wm * 32 + mi * 16 + (lane & 15)) * 80 +
                                           (lane >> 4) * 16 + kk * 32);
                LDSM_X4(fah[mi][0], fah[mi][1], fah[mi][2], fah[mi][3], sb + OAH + aoff);
                LDSM_X4(fal[mi][0], fal[mi][1], fal[mi][2], fal[mi][3], sb + OAL + aoff);
            }
            uint32_t fbsh[4][2], fbsl[4][2], fbth[4][2], fbtl[4][2];
#pragma unroll
            for (int np = 0; np < 2; np++) {
                int r = kk * 16 + (lane & 7) + ((lane >> 3) & 1) * 8;
                int cu = wn * 4 + np * 2 + (lane >> 4);
                uint32_t boff = (uint32_t)(r * 128 + ((cu ^ (r & 7)) << 4));
                LDSM_X4T(fbsh[2 * np][0], fbsh[2 * np][1], fbsh[2 * np + 1][0], fbsh[2 * np + 1][1], sb + obuf + 0 * B_TILE_B + boff);
                LDSM_X4T(fbsl[2 * np][0], fbsl[2 * np][1], fbsl[2 * np + 1][0], fbsl[2 * np + 1][1], sb + obuf + 1 * B_TILE_B + boff);
                LDSM_X4T(fbth[2 * np][0], fbth[2 * np][1], fbth[2 * np + 1][0], fbth[2 * np + 1][1], sb + obuf + 2 * B_TILE_B + boff);
                LDSM_X4T(fbtl[2 * np][0], fbtl[2 * np][1], fbtl[2 * np + 1][0], fbtl[2 * np + 1][1], sb + obuf + 3 * B_TILE_B + boff);
            }
#pragma unroll
            for (int mi = 0; mi < 2; mi++)
#pragma unroll
                for (int nj = 0; nj < 4; nj++) {
                    MMA_BF16(accS[mi][nj], fah[mi], fbsh[nj]);
                    MMA_BF16(accS[mi][nj], fah[mi], fbsl[nj]);
                    MMA_BF16(accS[mi][nj], fal[mi], fbsh[nj]);
                    MMA_BF16(accT[mi][nj], fah[mi], fbth[nj]);
                    MMA_BF16(accT[mi][nj], fah[mi], fbtl[nj]);
                    MMA_BF16(accT[mi][nj], fal[mi], fbth[nj]);
                }
        }
        __syncthreads();
    }

    int g = lane >> 2, c2 = (lane & 3) * 2;
#pragma unroll
    for (int mi = 0; mi < 2; mi++)
#pragma unroll
        for (int nj = 0; nj < 4; nj++) {
            int col = bn + wn * 32 + nj * 8 + c2;
            float2 bv = *(const float2*)(bias + col);
            int r0 = bm + wm * 32 + mi * 16 + g;
            if (r0 < M) {
                float2 os = {accS[mi][nj][0] + bv.x, accS[mi][nj][1] + bv.y};
                *(float2*)(S + (size_t)r0 * N + col) = os;
                float2 ot = {accT[mi][nj][0], accT[mi][nj][1]};
                *(float2*)(T + (size_t)r0 * N + col) = ot;
            }
            int r1 = r0 + 8;
            if (r1 < M) {
                float2 os = {accS[mi][nj][2] + bv.x, accS[mi][nj][3] + bv.y};
                *(float2*)(S + (size_t)r1 * N + col) = os;
                float2 ot = {accT[mi][nj][2], accT[mi][nj][3]};
                *(float2*)(T + (size_t)r1 * N + col) = ot;
            }
        }
}

// ---------------- fused layer-2 aggregation + node scores ----------------
__global__ void k_agg2_scores(const float* __restrict__ Wp) {
    int warps_per_blk = blockDim.x >> 5;
    int n = blockIdx.x * warps_per_blk + (threadIdx.x >> 5);
    if (n >= N_NODES) return;
    int lane = threadIdx.x & 31;
    int beg = g_rowptr[n], end = g_rowptr[n + 1];

    float4 acc0 = {0.f, 0.f, 0.f, 0.f};
    float4 acc1 = {0.f, 0.f, 0.f, 0.f};
    int j = beg;
    for (; j + 1 < end; j += 2) {
        int s0 = g_csr_src[j];
        int s1 = g_csr_src[j + 1];
        float4 v0 = __ldg(&((const float4*)(g_t2 + (size_t)s0 * 128))[lane]);
        float4 v1 = __ldg(&((const float4*)(g_t2 + (size_t)s1 * 128))[lane]);
        acc0.x += v0.x; acc0.y += v0.y; acc0.z += v0.z; acc0.w += v0.w;
        acc1.x += v1.x; acc1.y += v1.y; acc1.z += v1.z; acc1.w += v1.w;
    }
    if (j < end) {
        int s0 = g_csr_src[j];
        float4 v0 = __ldg(&((const float4*)(g_t2 + (size_t)s0 * 128))[lane]);
        acc0.x += v0.x; acc0.y += v0.y; acc0.z += v0.z; acc0.w += v0.w;
    }
    acc0.x += acc1.x; acc0.y += acc1.y; acc0.z += acc1.z; acc0.w += acc1.w;
    int deg = end - beg;
    float inv = (deg > 0) ? 1.f / (float)deg : 0.f;
    float4 sv = ((const float4*)(g_s2 + (size_t)n * 128))[lane];
    float4 h;
    h.x = sv.x + acc0.x * inv;
    h.y = sv.y + acc0.y * inv;
    h.z = sv.z + acc0.z * inv;
    h.w = sv.w + acc0.w * inv;

    float4 wa = __ldg(&((const float4*)Wp)[lane]);
    float4 wb = __ldg(&((const float4*)Wp)[lane + 32]);
    float a = h.x * wa.x + h.y * wa.y + h.z * wa.z + h.w * wa.w;
    float b = h.x * wb.x + h.y * wb.y + h.z * wb.z + h.w * wb.w;
#pragma unroll
    for (int off = 16; off; off >>= 1) {
        a += __shfl_down_sync(0xFFFFFFFFu, a, off);
        b += __shfl_down_sync(0xFFFFFFFFu, b, off);
    }
    if (lane == 0) { g_sA[n] = a; g_sB[n] = b; }
}

__global__ void k_edge_scores(const int* __restrict__ psrc, const int* __restrict__ pdst,
                              const int* __restrict__ nsrc, const int* __restrict__ ndst,
                              const float* __restrict__ bp, float* __restrict__ out,
                              int EP, int EN) {
    int i = blockIdx.x * blockDim.x + threadIdx.x;
    float b = bp[0];
    if (i < EP) {
        out[i] = g_sA[psrc[i]] + g_sB[pdst[i]] + b;
    } else if (i < EP + EN) {
        int j = i - EP;
        out[i] = g_sA[nsrc[j]] + g_sB[ndst[j]] + b;
    }
}

// ---------------- launch ----------------
extern "C" void kernel_launch(void* const* d_in, const int* in_sizes, int n_in,
                              void* d_out, int out_size) {
    const float* x    = (const float*)d_in[0];
    const int* msrc   = (const int*)d_in[1];
    const int* mdst   = (const int*)d_in[2];
    const int* psrc   = (const int*)d_in[3];
    const int* pdst   = (const int*)d_in[4];
    const int* nsrc   = (const int*)d_in[5];
    const int* ndst   = (const int*)d_in[6];
    const float* W1s  = (const float*)d_in[7];
    const float* W1n  = (const float*)d_in[8];
    const float* b1   = (const float*)d_in[9];
    const float* W2s  = (const float*)d_in[10];
    const float* W2n  = (const float*)d_in[11];
    const float* b2   = (const float*)d_in[12];
    const float* Wp   = (const float*)d_in[13];
    const float* bp   = (const float*)d_in[14];
    float* out = (float*)d_out;

    int E  = in_sizes[1];
    int EP = in_sizes[3];
    int EN = in_sizes[5];

    // lazy one-time stream/event creation (first call = correctness run, not captured)
    static cudaStream_t s2 = nullptr;
    static cudaEvent_t evFork = nullptr, evJoin = nullptr;
    static bool init_done = false;
    if (!init_done) {
        if (cudaStreamCreateWithFlags(&s2, cudaStreamNonBlocking) != cudaSuccess) s2 = nullptr;
        cudaEventCreateWithFlags(&evFork, cudaEventDisableTiming);
        cudaEventCreateWithFlags(&evJoin, cudaEventDisableTiming);
        init_done = true;
    }
    cudaStream_t sU = s2 ? s2 : (cudaStream_t)0;

    float *p_neigh1, *p_u, *p_h1, *p_s2, *p_t2;
    cudaGetSymbolAddress((void**)&p_neigh1, g_neigh1);
    cudaGetSymbolAddress((void**)&p_u,      g_u);
    cudaGetSymbolAddress((void**)&p_h1,     g_h1);
    cudaGetSymbolAddress((void**)&p_s2,     g_s2);
    cudaGetSymbolAddress((void**)&p_t2,     g_t2);

    __nv_bfloat16 *w1sh, *w1sl, *w1nh, *w1nl, *w2sh, *w2sl, *w2nh, *w2nl;
    cudaGetSymbolAddress((void**)&w1sh, g_w1s_h);
    cudaGetSymbolAddress((void**)&w1sl, g_w1s_l);
    cudaGetSymbolAddress((void**)&w1nh, g_w1n_h);
    cudaGetSymbolAddress((void**)&w1nl, g_w1n_l);
    cudaGetSymbolAddress((void**)&w2sh, g_w2s_h);
    cudaGetSymbolAddress((void**)&w2sl, g_w2s_l);
    cudaGetSymbolAddress((void**)&w2nh, g_w2n_h);
    cudaGetSymbolAddress((void**)&w2nl, g_w2n_l);

    const int SMEM_SINGLE = 2 * A_TILE_B + 2 * 2 * B_TILE_B;  // 36864
    const int SMEM_PAIR   = 2 * A_TILE_B + 2 * 4 * B_TILE_B;  // 53248
    cudaFuncSetAttribute(k_mm_single<false, false>, cudaFuncAttributeMaxDynamicSharedMemorySize, SMEM_SINGLE);
    cudaFuncSetAttribute(k_mm_single<true, true>,   cudaFuncAttributeMaxDynamicSharedMemorySize, SMEM_SINGLE);
    cudaFuncSetAttribute(k_mm_pair, cudaFuncAttributeMaxDynamicSharedMemorySize, SMEM_PAIR);

    // prep (cnt zero + weight split)
    k_wprep_all<<<(4 * 32768 + 255) / 256, 256>>>(W1s, W1n, W2s, W2n);

    // fork: u = x@W1s + b1 on side stream, overlapped with CSR build + agg
    if (s2) {
        cudaEventRecord(evFork, 0);
        cudaStreamWaitEvent(sU, evFork, 0);
    }
    {
        dim3 grid(D_HID / 64, (N_NODES + 127) / 128);
        k_mm_single<false, false><<<grid, 256, SMEM_SINGLE, sU>>>(
            x, w1sh, w1sl, b1, nullptr, p_u, N_NODES, D_HID, D_IN);
    }
    if (s2) cudaEventRecord(evJoin, sU);

    // main stream: CSR build + layer-1 aggregation
    k_hist<<<(E + 255) / 256, 256>>>(mdst, E);
    k_scan<<<1, 1024>>>();
    k_fill<<<(E + 255) / 256, 256>>>(msrc, mdst, E);
    k_agg128<<<(N_NODES + 7) / 8, 256>>>(x, p_neigh1);

    // join, then h1 = relu(u + n1@W1n)
    if (s2) cudaStreamWaitEvent((cudaStream_t)0, evJoin, 0);
    {
        dim3 grid(D_HID / 64, (N_NODES + 127) / 128);
        k_mm_single<true, true><<<grid, 256, SMEM_SINGLE>>>(
            p_neigh1, w1nh, w1nl, nullptr, p_u, p_h1, N_NODES, D_HID, D_IN);
    }

    // layer 2: project then aggregate
    {
        dim3 grid(D_OUT / 64, (N_NODES + 127) / 128);
        k_mm_pair<<<grid, 256, SMEM_PAIR>>>(p_h1, w2sh, w2sl, w2nh, w2nl,
                                            b2, p_s2, p_t2, N_NODES, D_OUT, D_HID);
    }
    k_agg2_scores<<<(N_NODES + 7) / 8, 256>>>(Wp);

    // edge scoring
    k_edge_scores<<<(EP + EN + 255) / 256, 256>>>(psrc, pdst, nsrc, ndst, bp, out, EP, EN);
}

// round 11
// speedup vs baseline: 1.3429x; 1.3429x over previous
#include <cuda_runtime.h>
#include <cuda_bf16.h>
#include <cstdint>

#define N_NODES 50000
#define MAX_E   800000
#define D_IN    128
#define D_HID   256
#define D_OUT   128
#define NBLK_SCAN ((N_NODES + 1023) / 1024)   // 49

// ---------------- scratch (static device globals; no allocation) ----------------
__device__ float g_neigh1[(size_t)N_NODES * D_IN];
__device__ float g_h1[(size_t)N_NODES * D_HID];
__device__ float g_s2[(size_t)N_NODES * D_OUT];
__device__ float g_t2[(size_t)N_NODES * D_OUT];
__device__ float g_sA[N_NODES];
__device__ float g_sB[N_NODES];
__device__ int   g_cnt[N_NODES];
__device__ int   g_rowptr[N_NODES + 1];
__device__ int   g_cursor[N_NODES];
__device__ int   g_csr_src[MAX_E];
__device__ int   g_blksum[64];

// pre-split bf16 weights, same (K,N) layout as the fp32 originals
__device__ __nv_bfloat16 g_w1s_h[D_IN * D_HID], g_w1s_l[D_IN * D_HID];
__device__ __nv_bfloat16 g_w1n_h[D_IN * D_HID], g_w1n_l[D_IN * D_HID];
__device__ __nv_bfloat16 g_w2s_h[D_HID * D_OUT], g_w2s_l[D_HID * D_OUT];
__device__ __nv_bfloat16 g_w2n_h[D_HID * D_OUT], g_w2n_l[D_HID * D_OUT];

// ---------------- helpers ----------------
__device__ __forceinline__ uint32_t smem_u32(const void* p) {
    uint32_t a;
    asm("{ .reg .u64 t; cvta.to.shared.u64 t, %1; cvt.u32.u64 %0, t; }" : "=r"(a) : "l"(p));
    return a;
}
__device__ __forceinline__ uint32_t bpack(__nv_bfloat16 a, __nv_bfloat16 b) {
    return (uint32_t)__bfloat16_as_ushort(a) | ((uint32_t)__bfloat16_as_ushort(b) << 16);
}
__device__ __forceinline__ void split4(float4 v, uint32_t* h, uint32_t* l) {
    __nv_bfloat16 hx = __float2bfloat16_rn(v.x);
    __nv_bfloat16 hy = __float2bfloat16_rn(v.y);
    __nv_bfloat16 hz = __float2bfloat16_rn(v.z);
    __nv_bfloat16 hw = __float2bfloat16_rn(v.w);
    h[0] = bpack(hx, hy);
    h[1] = bpack(hz, hw);
    __nv_bfloat16 lx = __float2bfloat16_rn(v.x - __bfloat162float(hx));
    __nv_bfloat16 ly = __float2bfloat16_rn(v.y - __bfloat162float(hy));
    __nv_bfloat16 lz = __float2bfloat16_rn(v.z - __bfloat162float(hz));
    __nv_bfloat16 lw = __float2bfloat16_rn(v.w - __bfloat162float(hw));
    l[0] = bpack(lx, ly);
    l[1] = bpack(lz, lw);
}

#define LDSM_X4(r0, r1, r2, r3, addr) \
    asm volatile("ldmatrix.sync.aligned.m8n8.x4.shared.b16 {%0,%1,%2,%3}, [%4];" \
                 : "=r"(r0), "=r"(r1), "=r"(r2), "=r"(r3) : "r"(addr))
#define LDSM_X4T(r0, r1, r2, r3, addr) \
    asm volatile("ldmatrix.sync.aligned.m8n8.x4.trans.shared.b16 {%0,%1,%2,%3}, [%4];" \
                 : "=r"(r0), "=r"(r1), "=r"(r2), "=r"(r3) : "r"(addr))
#define MMA_BF16(c, a, b) \
    asm volatile("mma.sync.aligned.m16n8k16.row.col.f32.bf16.bf16.f32 " \
                 "{%0,%1,%2,%3}, {%4,%5,%6,%7}, {%8,%9}, {%0,%1,%2,%3};" \
                 : "+f"((c)[0]), "+f"((c)[1]), "+f"((c)[2]), "+f"((c)[3]) \
                 : "r"((a)[0]), "r"((a)[1]), "r"((a)[2]), "r"((a)[3]), \
                   "r"((b)[0]), "r"((b)[1]))
#define CP_ASYNC16(saddr, gptr) \
    asm volatile("cp.async.cg.shared.global [%0], [%1], 16;" :: "r"(saddr), "l"(gptr))
#define CP_COMMIT() asm volatile("cp.async.commit_group;")
#define CP_WAIT(n)  asm volatile("cp.async.wait_group %0;" :: "n"(n))

// ---------------- CSR build ----------------
__global__ void k_hist(const int* __restrict__ dst, int E) {
    int e = blockIdx.x * blockDim.x + threadIdx.x;
    if (e < E) atomicAdd(&g_cnt[dst[e]], 1);
}

// multi-block scan: phase 1 — per-block sums
__global__ void k_scan1() {
    __shared__ int sh[1024];
    int t = threadIdx.x;
    int idx = blockIdx.x * 1024 + t;
    sh[t] = (idx < N_NODES) ? g_cnt[idx] : 0;
    __syncthreads();
#pragma unroll
    for (int off = 512; off > 0; off >>= 1) {
        if (t < off) sh[t] += sh[t + off];
        __syncthreads();
    }
    if (t == 0) g_blksum[blockIdx.x] = sh[0];
}

// phase 2 — scan the 49 block sums (one block of 64 threads)
__global__ void k_scan2() {
    __shared__ int sh[64];
    int t = threadIdx.x;
    int v = (t < NBLK_SCAN) ? g_blksum[t] : 0;
    sh[t] = v;
    __syncthreads();
#pragma unroll
    for (int off = 1; off < 64; off <<= 1) {
        int u = (t >= off) ? sh[t - off] : 0;
        __syncthreads();
        sh[t] += u;
        __syncthreads();
    }
    if (t < NBLK_SCAN) g_blksum[t] = sh[t] - v;   // exclusive
    if (t == 0) g_rowptr[N_NODES] = sh[NBLK_SCAN - 1];
}

// phase 3 — in-block exclusive scan + block offset -> rowptr/cursor
__global__ void k_scan3() {
    __shared__ int sh[1024];
    int t = threadIdx.x;
    int idx = blockIdx.x * 1024 + t;
    int v = (idx < N_NODES) ? g_cnt[idx] : 0;
    sh[t] = v;
    __syncthreads();
#pragma unroll
    for (int off = 1; off < 1024; off <<= 1) {
        int u = (t >= off) ? sh[t - off] : 0;
        __syncthreads();
        sh[t] += u;
        __syncthreads();
    }
    if (idx < N_NODES) {
        int ex = sh[t] - v + g_blksum[blockIdx.x];
        g_rowptr[idx] = ex;
        g_cursor[idx] = ex;
    }
}

__global__ void k_fill(const int* __restrict__ src, const int* __restrict__ dst, int E) {
    int e = blockIdx.x * blockDim.x + threadIdx.x;
    if (e < E) {
        int d = dst[e];
        int pos = atomicAdd(&g_cursor[d], 1);
        g_csr_src[pos] = src[e];
    }
}

// ---------------- layer-1 aggregation (unrolled x2) ----------------
__global__ void k_agg128(const float* __restrict__ feat, float* __restrict__ out) {
    int warps_per_blk = blockDim.x >> 5;
    int n = blockIdx.x * warps_per_blk + (threadIdx.x >> 5);
    if (n >= N_NODES) return;
    int lane = threadIdx.x & 31;
    int beg = g_rowptr[n], end = g_rowptr[n + 1];

    float4 acc0 = {0.f, 0.f, 0.f, 0.f};
    float4 acc1 = {0.f, 0.f, 0.f, 0.f};
    int j = beg;
    for (; j + 1 < end; j += 2) {
        int s0 = g_csr_src[j];
        int s1 = g_csr_src[j + 1];
        float4 v0 = __ldg(&((const float4*)(feat + (size_t)s0 * 128))[lane]);
        float4 v1 = __ldg(&((const float4*)(feat + (size_t)s1 * 128))[lane]);
        acc0.x += v0.x; acc0.y += v0.y; acc0.z += v0.z; acc0.w += v0.w;
        acc1.x += v1.x; acc1.y += v1.y; acc1.z += v1.z; acc1.w += v1.w;
    }
    if (j < end) {
        int s0 = g_csr_src[j];
        float4 v0 = __ldg(&((const float4*)(feat + (size_t)s0 * 128))[lane]);
        acc0.x += v0.x; acc0.y += v0.y; acc0.z += v0.z; acc0.w += v0.w;
    }
    acc0.x += acc1.x; acc0.y += acc1.y; acc0.z += acc1.z; acc0.w += acc1.w;
    int deg = end - beg;
    float inv = (deg > 0) ? 1.f / (float)deg : 0.f;
    float4 o = {acc0.x * inv, acc0.y * inv, acc0.z * inv, acc0.w * inv};
    ((float4*)(out + (size_t)n * 128))[lane] = o;
}

// ---------------- weight split + cnt zeroing, one launch ----------------
__global__ void k_wprep_all(
    const float* __restrict__ W1s, const float* __restrict__ W1n,
    const float* __restrict__ W2s, const float* __restrict__ W2n)
{
    int i = blockIdx.x * blockDim.x + threadIdx.x;
    if (i < N_NODES) g_cnt[i] = 0;
    if (i >= 4 * 32768) return;
    int a = i >> 15, r = i & 32767;
    const float* W = (a == 0) ? W1s : (a == 1) ? W1n : (a == 2) ? W2s : W2n;
    __nv_bfloat16* hi = (a == 0) ? g_w1s_h : (a == 1) ? g_w1n_h : (a == 2) ? g_w2s_h : g_w2n_h;
    __nv_bfloat16* lo = (a == 0) ? g_w1s_l : (a == 1) ? g_w1n_l : (a == 2) ? g_w2s_l : g_w2n_l;
    float w = W[r];
    __nv_bfloat16 h = __float2bfloat16_rn(w);
    hi[r] = h;
    lo[r] = __float2bfloat16_rn(w - __bfloat162float(h));
}

// ================= bf16x3 mma.sync GEMMs: swizzled-B double-buffer (round-8 proven) =================
#define A_TILE_B 10240
#define B_TILE_B 4096

// -------- layer 1: C = relu(A1@B1 + A2@B2 + bias) --------
__global__ void __launch_bounds__(256) k_mm_dual(
    const float* __restrict__ A1, const float* __restrict__ A2,
    const __nv_bfloat16* __restrict__ B1h, const __nv_bfloat16* __restrict__ B1l,
    const __nv_bfloat16* __restrict__ B2h, const __nv_bfloat16* __restrict__ B2l,
    const float* __restrict__ bias, float* __restrict__ C,
    int M, int N, int K)
{
    extern __shared__ char smem[];
    const int OA1H = 0, OA1L = A_TILE_B, OA2H = 2 * A_TILE_B, OA2L = 3 * A_TILE_B;
    const int OB_BASE = 4 * A_TILE_B;
    uint32_t sb = smem_u32(smem);

    int tid = threadIdx.x, lane = tid & 31, wid = tid >> 5;
    int wm = wid & 3, wn = wid >> 2;
    int bm = blockIdx.y * 128, bn = blockIdx.x * 64;
    const int nch = K >> 5;

    int brow = tid >> 3, bseg = tid & 7;
    uint32_t bso = (uint32_t)(brow * 128 + ((bseg ^ (brow & 7)) << 4));
    const __nv_bfloat16* gB[4] = {B1h, B1l, B2h, B2l};

    float acc[2][4][4];
#pragma unroll
    for (int i = 0; i < 2; i++)
#pragma unroll
        for (int j = 0; j < 4; j++)
#pragma unroll
            for (int q = 0; q < 4; q++) acc[i][j][q] = 0.f;

    {
        size_t ge = (size_t)brow * N + bn + bseg * 8;
#pragma unroll
        for (int t = 0; t < 4; t++)
            CP_ASYNC16(sb + OB_BASE + t * B_TILE_B + bso, gB[t] + ge);
        CP_COMMIT();
    }

    for (int chunk = 0; chunk < nch; chunk++) {
        int k0 = chunk << 5;
        int obuf = OB_BASE + (chunk & 1) * 4 * B_TILE_B;

#pragma unroll
        for (int q = 0; q < 4; q++) {
            int slot = tid + q * 256;
            int row = slot >> 3, k4 = (slot & 7) * 4;
            int gr = bm + row;
            float4 v1 = {0.f, 0.f, 0.f, 0.f}, v2 = {0.f, 0.f, 0.f, 0.f};
            if (gr < M) {
                v1 = *(const float4*)(A1 + (size_t)gr * K + k0 + k4);
                v2 = *(const float4*)(A2 + (size_t)gr * K + k0 + k4);
            }
            uint32_t h[2], l[2];
            int si = row * 20 + (k4 >> 1);
            split4(v1, h, l);
            ((uint32_t*)(smem + OA1H))[si] = h[0];
            ((uint32_t*)(smem + OA1H))[si + 1] = h[1];
            ((uint32_t*)(smem + OA1L))[si] = l[0];
            ((uint32_t*)(smem + OA1L))[si + 1] = l[1];
            split4(v2, h, l);
            ((uint32_t*)(smem + OA2H))[si] = h[0];
            ((uint32_t*)(smem + OA2H))[si + 1] = h[1];
            ((uint32_t*)(smem + OA2L))[si] = l[0];
            ((uint32_t*)(smem + OA2L))[si + 1] = l[1];
        }

        if (chunk + 1 < nch) {
            int nbuf = OB_BASE + ((chunk + 1) & 1) * 4 * B_TILE_B;
            size_t ge = (size_t)(((chunk + 1) << 5) + brow) * N + bn + bseg * 8;
#pragma unroll
            for (int t = 0; t < 4; t++)
                CP_ASYNC16(sb + nbuf + t * B_TILE_B + bso, gB[t] + ge);
            CP_COMMIT();
            CP_WAIT(1);
        } else {
            CP_WAIT(0);
        }
        __syncthreads();

#pragma unroll
        for (int kk = 0; kk < 2; kk++) {
            uint32_t fa1h[2][4], fa1l[2][4], fa2h[2][4], fa2l[2][4];
#pragma unroll
            for (int mi = 0; mi < 2; mi++) {
                uint32_t aoff = (uint32_t)((wm * 32 + mi * 16 + (lane & 15)) * 80 +
                                           (lane >> 4) * 16 + kk * 32);
                LDSM_X4(fa1h[mi][0], fa1h[mi][1], fa1h[mi][2], fa1h[mi][3], sb + OA1H + aoff);
                LDSM_X4(fa1l[mi][0], fa1l[mi][1], fa1l[mi][2], fa1l[mi][3], sb + OA1L + aoff);
                LDSM_X4(fa2h[mi][0], fa2h[mi][1], fa2h[mi][2], fa2h[mi][3], sb + OA2H + aoff);
                LDSM_X4(fa2l[mi][0], fa2l[mi][1], fa2l[mi][2], fa2l[mi][3], sb + OA2L + aoff);
            }
            uint32_t fb1h[4][2], fb1l[4][2], fb2h[4][2], fb2l[4][2];
#pragma unroll
            for (int np = 0; np < 2; np++) {
                int r = kk * 16 + (lane & 7) + ((lane >> 3) & 1) * 8;
                int cu = wn * 4 + np * 2 + (lane >> 4);
                uint32_t boff = (uint32_t)(r * 128 + ((cu ^ (r & 7)) << 4));
                LDSM_X4T(fb1h[2 * np][0], fb1h[2 * np][1], fb1h[2 * np + 1][0], fb1h[2 * np + 1][1], sb + obuf + 0 * B_TILE_B + boff);
                LDSM_X4T(fb1l[2 * np][0], fb1l[2 * np][1], fb1l[2 * np + 1][0], fb1l[2 * np + 1][1], sb + obuf + 1 * B_TILE_B + boff);
                LDSM_X4T(fb2h[2 * np][0], fb2h[2 * np][1], fb2h[2 * np + 1][0], fb2h[2 * np + 1][1], sb + obuf + 2 * B_TILE_B + boff);
                LDSM_X4T(fb2l[2 * np][0], fb2l[2 * np][1], fb2l[2 * np + 1][0], fb2l[2 * np + 1][1], sb + obuf + 3 * B_TILE_B + boff);
            }
#pragma unroll
            for (int mi = 0; mi < 2; mi++)
#pragma unroll
                for (int nj = 0; nj < 4; nj++) {
                    MMA_BF16(acc[mi][nj], fa1h[mi], fb1h[nj]);
                    MMA_BF16(acc[mi][nj], fa1h[mi], fb1l[nj]);
                    MMA_BF16(acc[mi][nj], fa1l[mi], fb1h[nj]);
                    MMA_BF16(acc[mi][nj], fa2h[mi], fb2h[nj]);
                    MMA_BF16(acc[mi][nj], fa2h[mi], fb2l[nj]);
                    MMA_BF16(acc[mi][nj], fa2l[mi], fb2h[nj]);
                }
        }
        __syncthreads();
    }

    int g = lane >> 2, c2 = (lane & 3) * 2;
#pragma unroll
    for (int mi = 0; mi < 2; mi++)
#pragma unroll
        for (int nj = 0; nj < 4; nj++) {
            int col = bn + wn * 32 + nj * 8 + c2;
            float2 bv = *(const float2*)(bias + col);
            int r0 = bm + wm * 32 + mi * 16 + g;
            if (r0 < M) {
                float2 o;
                o.x = fmaxf(acc[mi][nj][0] + bv.x, 0.f);
                o.y = fmaxf(acc[mi][nj][1] + bv.y, 0.f);
                *(float2*)(C + (size_t)r0 * N + col) = o;
            }
            int r1 = r0 + 8;
            if (r1 < M) {
                float2 o;
                o.x = fmaxf(acc[mi][nj][2] + bv.x, 0.f);
                o.y = fmaxf(acc[mi][nj][3] + bv.y, 0.f);
                *(float2*)(C + (size_t)r1 * N + col) = o;
            }
        }
}

// -------- layer 2: S = A@Bs + bias, T = A@Bt --------
__global__ void __launch_bounds__(256) k_mm_pair(
    const float* __restrict__ A,
    const __nv_bfloat16* __restrict__ Bsh, const __nv_bfloat16* __restrict__ Bsl,
    const __nv_bfloat16* __restrict__ Bth, const __nv_bfloat16* __restrict__ Btl,
    const float* __restrict__ bias, float* __restrict__ S, float* __restrict__ T,
    int M, int N, int K)
{
    extern __shared__ char smem[];
    const int OAH = 0, OAL = A_TILE_B;
    const int OB_BASE = 2 * A_TILE_B;
    uint32_t sb = smem_u32(smem);

    int tid = threadIdx.x, lane = tid & 31, wid = tid >> 5;
    int wm = wid & 3, wn = wid >> 2;
    int bm = blockIdx.y * 128, bn = blockIdx.x * 64;
    const int nch = K >> 5;

    int brow = tid >> 3, bseg = tid & 7;
    uint32_t bso = (uint32_t)(brow * 128 + ((bseg ^ (brow & 7)) << 4));
    const __nv_bfloat16* gB[4] = {Bsh, Bsl, Bth, Btl};

    float accS[2][4][4], accT[2][4][4];
#pragma unroll
    for (int i = 0; i < 2; i++)
#pragma unroll
        for (int j = 0; j < 4; j++)
#pragma unroll
            for (int q = 0; q < 4; q++) { accS[i][j][q] = 0.f; accT[i][j][q] = 0.f; }

    {
        size_t ge = (size_t)brow * N + bn + bseg * 8;
#pragma unroll
        for (int t = 0; t < 4; t++)
            CP_ASYNC16(sb + OB_BASE + t * B_TILE_B + bso, gB[t] + ge);
        CP_COMMIT();
    }

    for (int chunk = 0; chunk < nch; chunk++) {
        int k0 = chunk << 5;
        int obuf = OB_BASE + (chunk & 1) * 4 * B_TILE_B;

#pragma unroll
        for (int q = 0; q < 4; q++) {
            int slot = tid + q * 256;
            int row = slot >> 3, k4 = (slot & 7) * 4;
            int gr = bm + row;
            float4 v = {0.f, 0.f, 0.f, 0.f};
            if (gr < M) v = *(const float4*)(A + (size_t)gr * K + k0 + k4);
            uint32_t h[2], l[2];
            split4(v, h, l);
            int si = row * 20 + (k4 >> 1);
            ((uint32_t*)(smem + OAH))[si] = h[0];
            ((uint32_t*)(smem + OAH))[si + 1] = h[1];
            ((uint32_t*)(smem + OAL))[si] = l[0];
            ((uint32_t*)(smem + OAL))[si + 1] = l[1];
        }

        if (chunk + 1 < nch) {
            int nbuf = OB_BASE + ((chunk + 1) & 1) * 4 * B_TILE_B;
            size_t ge = (size_t)(((chunk + 1) << 5) + brow) * N + bn + bseg * 8;
#pragma unroll
            for (int t = 0; t < 4; t++)
                CP_ASYNC16(sb + nbuf + t * B_TILE_B + bso, gB[t] + ge);
            CP_COMMIT();
            CP_WAIT(1);
        } else {
            CP_WAIT(0);
        }
        __syncthreads();

#pragma unroll
        for (int kk = 0; kk < 2; kk++) {
            uint32_t fah[2][4], fal[2][4];
#pragma unroll
            for (int mi = 0; mi < 2; mi++) {
                uint32_t aoff = (uint32_t)((wm * 32 + mi * 16 + (lane & 15)) * 80 +
                                           (lane >> 4) * 16 + kk * 32);
                LDSM_X4(fah[mi][0], fah[mi][1], fah[mi][2], fah[mi][3], sb + OAH + aoff);
                LDSM_X4(fal[mi][0], fal[mi][1], fal[mi][2], fal[mi][3], sb + OAL + aoff);
            }
            uint32_t fbsh[4][2], fbsl[4][2], fbth[4][2], fbtl[4][2];
#pragma unroll
            for (int np = 0; np < 2; np++) {
                int r = kk * 16 + (lane & 7) + ((lane >> 3) & 1) * 8;
                int cu = wn * 4 + np * 2 + (lane >> 4);
                uint32_t boff = (uint32_t)(r * 128 + ((cu ^ (r & 7)) << 4));
                LDSM_X4T(fbsh[2 * np][0], fbsh[2 * np][1], fbsh[2 * np + 1][0], fbsh[2 * np + 1][1], sb + obuf + 0 * B_TILE_B + boff);
                LDSM_X4T(fbsl[2 * np][0], fbsl[2 * np][1], fbsl[2 * np + 1][0], fbsl[2 * np + 1][1], sb + obuf + 1 * B_TILE_B + boff);
                LDSM_X4T(fbth[2 * np][0], fbth[2 * np][1], fbth[2 * np + 1][0], fbth[2 * np + 1][1], sb + obuf + 2 * B_TILE_B + boff);
                LDSM_X4T(fbtl[2 * np][0], fbtl[2 * np][1], fbtl[2 * np + 1][0], fbtl[2 * np + 1][1], sb + obuf + 3 * B_TILE_B + boff);
            }
#pragma unroll
            for (int mi = 0; mi < 2; mi++)
#pragma unroll
                for (int nj = 0; nj < 4; nj++) {
                    MMA_BF16(accS[mi][nj], fah[mi], fbsh[nj]);
                    MMA_BF16(accS[mi][nj], fah[mi], fbsl[nj]);
                    MMA_BF16(accS[mi][nj], fal[mi], fbsh[nj]);
                    MMA_BF16(accT[mi][nj], fah[mi], fbth[nj]);
                    MMA_BF16(accT[mi][nj], fah[mi], fbtl[nj]);
                    MMA_BF16(accT[mi][nj], fal[mi], fbth[nj]);
                }
        }
        __syncthreads();
    }

    int g = lane >> 2, c2 = (lane & 3) * 2;
#pragma unroll
    for (int mi = 0; mi < 2; mi++)
#pragma unroll
        for (int nj = 0; nj < 4; nj++) {
            int col = bn + wn * 32 + nj * 8 + c2;
            float2 bv = *(const float2*)(bias + col);
            int r0 = bm + wm * 32 + mi * 16 + g;
            if (r0 < M) {
                float2 os = {accS[mi][nj][0] + bv.x, accS[mi][nj][1] + bv.y};
                *(float2*)(S + (size_t)r0 * N + col) = os;
                float2 ot = {accT[mi][nj][0], accT[mi][nj][1]};
                *(float2*)(T + (size_t)r0 * N + col) = ot;
            }
            int r1 = r0 + 8;
            if (r1 < M) {
                float2 os = {accS[mi][nj][2] + bv.x, accS[mi][nj][3] + bv.y};
                *(float2*)(S + (size_t)r1 * N + col) = os;
                float2 ot = {accT[mi][nj][2], accT[mi][nj][3]};
                *(float2*)(T + (size_t)r1 * N + col) = ot;
            }
        }
}

// ---------------- fused layer-2 aggregation + node scores ----------------
__global__ void k_agg2_scores(const float* __restrict__ Wp) {
    int warps_per_blk = blockDim.x >> 5;
    int n = blockIdx.x * warps_per_blk + (threadIdx.x >> 5);
    if (n >= N_NODES) return;
    int lane = threadIdx.x & 31;
    int beg = g_rowptr[n], end = g_rowptr[n + 1];

    float4 acc0 = {0.f, 0.f, 0.f, 0.f};
    float4 acc1 = {0.f, 0.f, 0.f, 0.f};
    int j = beg;
    for (; j + 1 < end; j += 2) {
        int s0 = g_csr_src[j];
        int s1 = g_csr_src[j + 1];
        float4 v0 = __ldg(&((const float4*)(g_t2 + (size_t)s0 * 128))[lane]);
        float4 v1 = __ldg(&((const float4*)(g_t2 + (size_t)s1 * 128))[lane]);
        acc0.x += v0.x; acc0.y += v0.y; acc0.z += v0.z; acc0.w += v0.w;
        acc1.x += v1.x; acc1.y += v1.y; acc1.z += v1.z; acc1.w += v1.w;
    }
    if (j < end) {
        int s0 = g_csr_src[j];
        float4 v0 = __ldg(&((const float4*)(g_t2 + (size_t)s0 * 128))[lane]);
        acc0.x += v0.x; acc0.y += v0.y; acc0.z += v0.z; acc0.w += v0.w;
    }
    acc0.x += acc1.x; acc0.y += acc1.y; acc0.z += acc1.z; acc0.w += acc1.w;
    int deg = end - beg;
    float inv = (deg > 0) ? 1.f / (float)deg : 0.f;
    float4 sv = ((const float4*)(g_s2 + (size_t)n * 128))[lane];
    float4 h;
    h.x = sv.x + acc0.x * inv;
    h.y = sv.y + acc0.y * inv;
    h.z = sv.z + acc0.z * inv;
    h.w = sv.w + acc0.w * inv;

    float4 wa = __ldg(&((const float4*)Wp)[lane]);
    float4 wb = __ldg(&((const float4*)Wp)[lane + 32]);
    float a = h.x * wa.x + h.y * wa.y + h.z * wa.z + h.w * wa.w;
    float b = h.x * wb.x + h.y * wb.y + h.z * wb.z + h.w * wb.w;
#pragma unroll
    for (int off = 16; off; off >>= 1) {
        a += __shfl_down_sync(0xFFFFFFFFu, a, off);
        b += __shfl_down_sync(0xFFFFFFFFu, b, off);
    }
    if (lane == 0) { g_sA[n] = a; g_sB[n] = b; }
}

__global__ void k_edge_scores(const int* __restrict__ psrc, const int* __restrict__ pdst,
                              const int* __restrict__ nsrc, const int* __restrict__ ndst,
                              const float* __restrict__ bp, float* __restrict__ out,
                              int EP, int EN) {
    int i = blockIdx.x * blockDim.x + threadIdx.x;
    float b = bp[0];
    if (i < EP) {
        out[i] = g_sA[psrc[i]] + g_sB[pdst[i]] + b;
    } else if (i < EP + EN) {
        int j = i - EP;
        out[i] = g_sA[nsrc[j]] + g_sB[ndst[j]] + b;
    }
}

// ---------------- launch ----------------
extern "C" void kernel_launch(void* const* d_in, const int* in_sizes, int n_in,
                              void* d_out, int out_size) {
    const float* x    = (const float*)d_in[0];
    const int* msrc   = (const int*)d_in[1];
    const int* mdst   = (const int*)d_in[2];
    const int* psrc   = (const int*)d_in[3];
    const int* pdst   = (const int*)d_in[4];
    const int* nsrc   = (const int*)d_in[5];
    const int* ndst   = (const int*)d_in[6];
    const float* W1s  = (const float*)d_in[7];
    const float* W1n  = (const float*)d_in[8];
    const float* b1   = (const float*)d_in[9];
    const float* W2s  = (const float*)d_in[10];
    const float* W2n  = (const float*)d_in[11];
    const float* b2   = (const float*)d_in[12];
    const float* Wp   = (const float*)d_in[13];
    const float* bp   = (const float*)d_in[14];
    float* out = (float*)d_out;

    int E  = in_sizes[1];
    int EP = in_sizes[3];
    int EN = in_sizes[5];

    float *p_neigh1, *p_h1, *p_s2, *p_t2;
    cudaGetSymbolAddress((void**)&p_neigh1, g_neigh1);
    cudaGetSymbolAddress((void**)&p_h1,     g_h1);
    cudaGetSymbolAddress((void**)&p_s2,     g_s2);
    cudaGetSymbolAddress((void**)&p_t2,     g_t2);

    __nv_bfloat16 *w1sh, *w1sl, *w1nh, *w1nl, *w2sh, *w2sl, *w2nh, *w2nl;
    cudaGetSymbolAddress((void**)&w1sh, g_w1s_h);
    cudaGetSymbolAddress((void**)&w1sl, g_w1s_l);
    cudaGetSymbolAddress((void**)&w1nh, g_w1n_h);
    cudaGetSymbolAddress((void**)&w1nl, g_w1n_l);
    cudaGetSymbolAddress((void**)&w2sh, g_w2s_h);
    cudaGetSymbolAddress((void**)&w2sl, g_w2s_l);
    cudaGetSymbolAddress((void**)&w2nh, g_w2n_h);
    cudaGetSymbolAddress((void**)&w2nl, g_w2n_l);

    const int SMEM_DUAL = 4 * A_TILE_B + 2 * 4 * B_TILE_B;  // 73728
    const int SMEM_PAIR = 2 * A_TILE_B + 2 * 4 * B_TILE_B;  // 53248
    cudaFuncSetAttribute(k_mm_dual, cudaFuncAttributeMaxDynamicSharedMemorySize, SMEM_DUAL);
    cudaFuncSetAttribute(k_mm_pair, cudaFuncAttributeMaxDynamicSharedMemorySize, SMEM_PAIR);

    // prep (cnt zero + weight split), then CSR build with multi-block scan
    k_wprep_all<<<(4 * 32768 + 255) / 256, 256>>>(W1s, W1n, W2s, W2n);
    k_hist<<<(E + 255) / 256, 256>>>(mdst, E);
    k_scan1<<<NBLK_SCAN, 1024>>>();
    k_scan2<<<1, 64>>>();
    k_scan3<<<NBLK_SCAN, 1024>>>();
    k_fill<<<(E + 255) / 256, 256>>>(msrc, mdst, E);

    // layer 1
    k_agg128<<<(N_NODES + 7) / 8, 256>>>(x, p_neigh1);
    {
        dim3 grid(D_HID / 64, (N_NODES + 127) / 128);
        k_mm_dual<<<grid, 256, SMEM_DUAL>>>(x, p_neigh1, w1sh, w1sl, w1nh, w1nl,
                                            b1, p_h1, N_NODES, D_HID, D_IN);
    }
    // layer 2: project then aggregate
    {
        dim3 grid(D_OUT / 64, (N_NODES + 127) / 128);
        k_mm_pair<<<grid, 256, SMEM_PAIR>>>(p_h1, w2sh, w2sl, w2nh, w2nl,
                                            b2, p_s2, p_t2, N_NODES, D_OUT, D_HID);
    }
    k_agg2_scores<<<(N_NODES + 7) / 8, 256>>>(Wp);

    // edge scoring
    k_edge_scores<<<(EP + EN + 255) / 256, 256>>>(psrc, pdst, nsrc, ndst, bp, out, EP, EN);
}

// round 12
// speedup vs baseline: 1.3994x; 1.0421x over previous
#include <cuda_runtime.h>
#include <cuda_bf16.h>
#include <cstdint>

#define N_NODES 50000
#define MAX_E   800000
#define D_IN    128
#define D_HID   256
#define D_OUT   128
#define NBLK_SCAN ((N_NODES + 1023) / 1024)   // 49

// ---------------- scratch (static device globals; no allocation) ----------------
__device__ float g_neigh1[(size_t)N_NODES * D_IN];
__device__ float g_h1[(size_t)N_NODES * D_HID];
__device__ float g_s2[(size_t)N_NODES * D_OUT];
__device__ float g_t2[(size_t)N_NODES * D_OUT];
__device__ float g_sA[N_NODES];
__device__ float g_sB[N_NODES];
__device__ int   g_cnt[N_NODES];
__device__ int   g_rowptr[N_NODES + 1];
__device__ int   g_cursor[N_NODES];
__device__ int   g_csr_src[MAX_E];
__device__ int   g_blksum[64];

// pre-split bf16 weights, same (K,N) layout as the fp32 originals
__device__ __nv_bfloat16 g_w1s_h[D_IN * D_HID], g_w1s_l[D_IN * D_HID];
__device__ __nv_bfloat16 g_w1n_h[D_IN * D_HID], g_w1n_l[D_IN * D_HID];
__device__ __nv_bfloat16 g_w2s_h[D_HID * D_OUT], g_w2s_l[D_HID * D_OUT];
__device__ __nv_bfloat16 g_w2n_h[D_HID * D_OUT], g_w2n_l[D_HID * D_OUT];

// ---------------- helpers ----------------
__device__ __forceinline__ uint32_t smem_u32(const void* p) {
    uint32_t a;
    asm("{ .reg .u64 t; cvta.to.shared.u64 t, %1; cvt.u32.u64 %0, t; }" : "=r"(a) : "l"(p));
    return a;
}
__device__ __forceinline__ uint32_t bpack(__nv_bfloat16 a, __nv_bfloat16 b) {
    return (uint32_t)__bfloat16_as_ushort(a) | ((uint32_t)__bfloat16_as_ushort(b) << 16);
}
__device__ __forceinline__ void split4(float4 v, uint32_t* h, uint32_t* l) {
    __nv_bfloat16 hx = __float2bfloat16_rn(v.x);
    __nv_bfloat16 hy = __float2bfloat16_rn(v.y);
    __nv_bfloat16 hz = __float2bfloat16_rn(v.z);
    __nv_bfloat16 hw = __float2bfloat16_rn(v.w);
    h[0] = bpack(hx, hy);
    h[1] = bpack(hz, hw);
    __nv_bfloat16 lx = __float2bfloat16_rn(v.x - __bfloat162float(hx));
    __nv_bfloat16 ly = __float2bfloat16_rn(v.y - __bfloat162float(hy));
    __nv_bfloat16 lz = __float2bfloat16_rn(v.z - __bfloat162float(hz));
    __nv_bfloat16 lw = __float2bfloat16_rn(v.w - __bfloat162float(hw));
    l[0] = bpack(lx, ly);
    l[1] = bpack(lz, lw);
}

#define LDSM_X4(r0, r1, r2, r3, addr) \
    asm volatile("ldmatrix.sync.aligned.m8n8.x4.shared.b16 {%0,%1,%2,%3}, [%4];" \
                 : "=r"(r0), "=r"(r1), "=r"(r2), "=r"(r3) : "r"(addr))
#define LDSM_X4T(r0, r1, r2, r3, addr) \
    asm volatile("ldmatrix.sync.aligned.m8n8.x4.trans.shared.b16 {%0,%1,%2,%3}, [%4];" \
                 : "=r"(r0), "=r"(r1), "=r"(r2), "=r"(r3) : "r"(addr))
#define MMA_BF16(c, a, b) \
    asm volatile("mma.sync.aligned.m16n8k16.row.col.f32.bf16.bf16.f32 " \
                 "{%0,%1,%2,%3}, {%4,%5,%6,%7}, {%8,%9}, {%0,%1,%2,%3};" \
                 : "+f"((c)[0]), "+f"((c)[1]), "+f"((c)[2]), "+f"((c)[3]) \
                 : "r"((a)[0]), "r"((a)[1]), "r"((a)[2]), "r"((a)[3]), \
                   "r"((b)[0]), "r"((b)[1]))
#define CP_ASYNC16(saddr, gptr) \
    asm volatile("cp.async.cg.shared.global [%0], [%1], 16;" :: "r"(saddr), "l"(gptr))
#define CP_COMMIT() asm volatile("cp.async.commit_group;")
#define CP_WAIT(n)  asm volatile("cp.async.wait_group %0;" :: "n"(n))

// ---------------- CSR build ----------------
__global__ void k_hist(const int* __restrict__ dst, int E) {
    int e = blockIdx.x * blockDim.x + threadIdx.x;
    if (e < E) atomicAdd(&g_cnt[dst[e]], 1);
}

// multi-block scan: phase 1 — per-block sums
__global__ void k_scan1() {
    __shared__ int sh[1024];
    int t = threadIdx.x;
    int idx = blockIdx.x * 1024 + t;
    sh[t] = (idx < N_NODES) ? g_cnt[idx] : 0;
    __syncthreads();
#pragma unroll
    for (int off = 512; off > 0; off >>= 1) {
        if (t < off) sh[t] += sh[t + off];
        __syncthreads();
    }
    if (t == 0) g_blksum[blockIdx.x] = sh[0];
}

// phase 2 (merged): every block redundantly scans the 49 block sums, then
// does its in-block exclusive scan + offset -> rowptr/cursor.
__global__ void k_scan3() {
    __shared__ int sh[1024];
    __shared__ int bs[64];
    int t = threadIdx.x;

    // redundant 64-wide exclusive scan of block sums
    int bv = 0;
    if (t < 64) {
        bv = (t < NBLK_SCAN) ? g_blksum[t] : 0;
        bs[t] = bv;
    }
    __syncthreads();
#pragma unroll
    for (int off = 1; off < 64; off <<= 1) {
        int u = 0;
        if (t < 64 && t >= off) u = bs[t - off];
        __syncthreads();
        if (t < 64) bs[t] += u;
        __syncthreads();
    }
    // bs[i] now inclusive; exclusive offset for this block:
    int blk_off = (blockIdx.x == 0) ? 0 : bs[blockIdx.x - 1];
    if (blockIdx.x == 0 && t == 0) g_rowptr[N_NODES] = bs[NBLK_SCAN - 1];

    int idx = blockIdx.x * 1024 + t;
    int v = (idx < N_NODES) ? g_cnt[idx] : 0;
    sh[t] = v;
    __syncthreads();
#pragma unroll
    for (int off = 1; off < 1024; off <<= 1) {
        int u = (t >= off) ? sh[t - off] : 0;
        __syncthreads();
        sh[t] += u;
        __syncthreads();
    }
    if (idx < N_NODES) {
        int ex = sh[t] - v + blk_off;
        g_rowptr[idx] = ex;
        g_cursor[idx] = ex;
    }
}

__global__ void k_fill(const int* __restrict__ src, const int* __restrict__ dst, int E) {
    int e = blockIdx.x * blockDim.x + threadIdx.x;
    if (e < E) {
        int d = dst[e];
        int pos = atomicAdd(&g_cursor[d], 1);
        g_csr_src[pos] = src[e];
    }
}

// ---------------- layer-1 aggregation: half-warp per node, unrolled x2 ----------------
__global__ void k_agg128(const float* __restrict__ feat, float* __restrict__ out) {
    int halves_per_blk = blockDim.x >> 4;
    int n = blockIdx.x * halves_per_blk + (threadIdx.x >> 4);
    if (n >= N_NODES) return;
    int lane = threadIdx.x & 15;
    int beg = g_rowptr[n], end = g_rowptr[n + 1];

    float4 aA0 = {0.f, 0.f, 0.f, 0.f}, aB0 = {0.f, 0.f, 0.f, 0.f};
    float4 aA1 = {0.f, 0.f, 0.f, 0.f}, aB1 = {0.f, 0.f, 0.f, 0.f};
    int j = beg;
    for (; j + 1 < end; j += 2) {
        int s0 = g_csr_src[j];
        int s1 = g_csr_src[j + 1];
        const float4* r0 = (const float4*)(feat + (size_t)s0 * 128);
        const float4* r1 = (const float4*)(feat + (size_t)s1 * 128);
        float4 vA0 = __ldg(&r0[lane]);
        float4 vB0 = __ldg(&r0[lane + 16]);
        float4 vA1 = __ldg(&r1[lane]);
        float4 vB1 = __ldg(&r1[lane + 16]);
        aA0.x += vA0.x; aA0.y += vA0.y; aA0.z += vA0.z; aA0.w += vA0.w;
        aB0.x += vB0.x; aB0.y += vB0.y; aB0.z += vB0.z; aB0.w += vB0.w;
        aA1.x += vA1.x; aA1.y += vA1.y; aA1.z += vA1.z; aA1.w += vA1.w;
        aB1.x += vB1.x; aB1.y += vB1.y; aB1.z += vB1.z; aB1.w += vB1.w;
    }
    if (j < end) {
        int s0 = g_csr_src[j];
        const float4* r0 = (const float4*)(feat + (size_t)s0 * 128);
        float4 vA0 = __ldg(&r0[lane]);
        float4 vB0 = __ldg(&r0[lane + 16]);
        aA0.x += vA0.x; aA0.y += vA0.y; aA0.z += vA0.z; aA0.w += vA0.w;
        aB0.x += vB0.x; aB0.y += vB0.y; aB0.z += vB0.z; aB0.w += vB0.w;
    }
    aA0.x += aA1.x; aA0.y += aA1.y; aA0.z += aA1.z; aA0.w += aA1.w;
    aB0.x += aB1.x; aB0.y += aB1.y; aB0.z += aB1.z; aB0.w += aB1.w;
    int deg = end - beg;
    float inv = (deg > 0) ? 1.f / (float)deg : 0.f;
    float4* orow = (float4*)(out + (size_t)n * 128);
    float4 oA = {aA0.x * inv, aA0.y * inv, aA0.z * inv, aA0.w * inv};
    float4 oB = {aB0.x * inv, aB0.y * inv, aB0.z * inv, aB0.w * inv};
    orow[lane] = oA;
    orow[lane + 16] = oB;
}

// ---------------- weight split + cnt zeroing, one launch ----------------
__global__ void k_wprep_all(
    const float* __restrict__ W1s, const float* __restrict__ W1n,
    const float* __restrict__ W2s, const float* __restrict__ W2n)
{
    int i = blockIdx.x * blockDim.x + threadIdx.x;
    if (i < N_NODES) g_cnt[i] = 0;
    if (i >= 4 * 32768) return;
    int a = i >> 15, r = i & 32767;
    const float* W = (a == 0) ? W1s : (a == 1) ? W1n : (a == 2) ? W2s : W2n;
    __nv_bfloat16* hi = (a == 0) ? g_w1s_h : (a == 1) ? g_w1n_h : (a == 2) ? g_w2s_h : g_w2n_h;
    __nv_bfloat16* lo = (a == 0) ? g_w1s_l : (a == 1) ? g_w1n_l : (a == 2) ? g_w2s_l : g_w2n_l;
    float w = W[r];
    __nv_bfloat16 h = __float2bfloat16_rn(w);
    hi[r] = h;
    lo[r] = __float2bfloat16_rn(w - __bfloat162float(h));
}

// ================= bf16x3 mma.sync GEMMs: swizzled-B double-buffer (round-8 proven) =================
#define A_TILE_B 10240
#define B_TILE_B 4096

// -------- layer 1: C = relu(A1@B1 + A2@B2 + bias) --------
__global__ void __launch_bounds__(256) k_mm_dual(
    const float* __restrict__ A1, const float* __restrict__ A2,
    const __nv_bfloat16* __restrict__ B1h, const __nv_bfloat16* __restrict__ B1l,
    const __nv_bfloat16* __restrict__ B2h, const __nv_bfloat16* __restrict__ B2l,
    const float* __restrict__ bias, float* __restrict__ C,
    int M, int N, int K)
{
    extern __shared__ char smem[];
    const int OA1H = 0, OA1L = A_TILE_B, OA2H = 2 * A_TILE_B, OA2L = 3 * A_TILE_B;
    const int OB_BASE = 4 * A_TILE_B;
    uint32_t sb = smem_u32(smem);

    int tid = threadIdx.x, lane = tid & 31, wid = tid >> 5;
    int wm = wid & 3, wn = wid >> 2;
    int bm = blockIdx.y * 128, bn = blockIdx.x * 64;
    const int nch = K >> 5;

    int brow = tid >> 3, bseg = tid & 7;
    uint32_t bso = (uint32_t)(brow * 128 + ((bseg ^ (brow & 7)) << 4));
    const __nv_bfloat16* gB[4] = {B1h, B1l, B2h, B2l};

    float acc[2][4][4];
#pragma unroll
    for (int i = 0; i < 2; i++)
#pragma unroll
        for (int j = 0; j < 4; j++)
#pragma unroll
            for (int q = 0; q < 4; q++) acc[i][j][q] = 0.f;

    {
        size_t ge = (size_t)brow * N + bn + bseg * 8;
#pragma unroll
        for (int t = 0; t < 4; t++)
            CP_ASYNC16(sb + OB_BASE + t * B_TILE_B + bso, gB[t] + ge);
        CP_COMMIT();
    }

    for (int chunk = 0; chunk < nch; chunk++) {
        int k0 = chunk << 5;
        int obuf = OB_BASE + (chunk & 1) * 4 * B_TILE_B;

#pragma unroll
        for (int q = 0; q < 4; q++) {
            int slot = tid + q * 256;
            int row = slot >> 3, k4 = (slot & 7) * 4;
            int gr = bm + row;
            float4 v1 = {0.f, 0.f, 0.f, 0.f}, v2 = {0.f, 0.f, 0.f, 0.f};
            if (gr < M) {
                v1 = *(const float4*)(A1 + (size_t)gr * K + k0 + k4);
                v2 = *(const float4*)(A2 + (size_t)gr * K + k0 + k4);
            }
            uint32_t h[2], l[2];
            int si = row * 20 + (k4 >> 1);
            split4(v1, h, l);
            ((uint32_t*)(smem + OA1H))[si] = h[0];
            ((uint32_t*)(smem + OA1H))[si + 1] = h[1];
            ((uint32_t*)(smem + OA1L))[si] = l[0];
            ((uint32_t*)(smem + OA1L))[si + 1] = l[1];
            split4(v2, h, l);
            ((uint32_t*)(smem + OA2H))[si] = h[0];
            ((uint32_t*)(smem + OA2H))[si + 1] = h[1];
            ((uint32_t*)(smem + OA2L))[si] = l[0];
            ((uint32_t*)(smem + OA2L))[si + 1] = l[1];
        }

        if (chunk + 1 < nch) {
            int nbuf = OB_BASE + ((chunk + 1) & 1) * 4 * B_TILE_B;
            size_t ge = (size_t)(((chunk + 1) << 5) + brow) * N + bn + bseg * 8;
#pragma unroll
            for (int t = 0; t < 4; t++)
                CP_ASYNC16(sb + nbuf + t * B_TILE_B + bso, gB[t] + ge);
            CP_COMMIT();
            CP_WAIT(1);
        } else {
            CP_WAIT(0);
        }
        __syncthreads();

#pragma unroll
        for (int kk = 0; kk < 2; kk++) {
            uint32_t fa1h[2][4], fa1l[2][4], fa2h[2][4], fa2l[2][4];
#pragma unroll
            for (int mi = 0; mi < 2; mi++) {
                uint32_t aoff = (uint32_t)((wm * 32 + mi * 16 + (lane & 15)) * 80 +
                                           (lane >> 4) * 16 + kk * 32);
                LDSM_X4(fa1h[mi][0], fa1h[mi][1], fa1h[mi][2], fa1h[mi][3], sb + OA1H + aoff);
                LDSM_X4(fa1l[mi][0], fa1l[mi][1], fa1l[mi][2], fa1l[mi][3], sb + OA1L + aoff);
                LDSM_X4(fa2h[mi][0], fa2h[mi][1], fa2h[mi][2], fa2h[mi][3], sb + OA2H + aoff);
                LDSM_X4(fa2l[mi][0], fa2l[mi][1], fa2l[mi][2], fa2l[mi][3], sb + OA2L + aoff);
            }
            uint32_t fb1h[4][2], fb1l[4][2], fb2h[4][2], fb2l[4][2];
#pragma unroll
            for (int np = 0; np < 2; np++) {
                int r = kk * 16 + (lane & 7) + ((lane >> 3) & 1) * 8;
                int cu = wn * 4 + np * 2 + (lane >> 4);
                uint32_t boff = (uint32_t)(r * 128 + ((cu ^ (r & 7)) << 4));
                LDSM_X4T(fb1h[2 * np][0], fb1h[2 * np][1], fb1h[2 * np + 1][0], fb1h[2 * np + 1][1], sb + obuf + 0 * B_TILE_B + boff);
                LDSM_X4T(fb1l[2 * np][0], fb1l[2 * np][1], fb1l[2 * np + 1][0], fb1l[2 * np + 1][1], sb + obuf + 1 * B_TILE_B + boff);
                LDSM_X4T(fb2h[2 * np][0], fb2h[2 * np][1], fb2h[2 * np + 1][0], fb2h[2 * np + 1][1], sb + obuf + 2 * B_TILE_B + boff);
                LDSM_X4T(fb2l[2 * np][0], fb2l[2 * np][1], fb2l[2 * np + 1][0], fb2l[2 * np + 1][1], sb + obuf + 3 * B_TILE_B + boff);
            }
#pragma unroll
            for (int mi = 0; mi < 2; mi++)
#pragma unroll
                for (int nj = 0; nj < 4; nj++) {
                    MMA_BF16(acc[mi][nj], fa1h[mi], fb1h[nj]);
                    MMA_BF16(acc[mi][nj], fa1h[mi], fb1l[nj]);
                    MMA_BF16(acc[mi][nj], fa1l[mi], fb1h[nj]);
                    MMA_BF16(acc[mi][nj], fa2h[mi], fb2h[nj]);
                    MMA_BF16(acc[mi][nj], fa2h[mi], fb2l[nj]);
                    MMA_BF16(acc[mi][nj], fa2l[mi], fb2h[nj]);
                }
        }
        __syncthreads();
    }

    int g = lane >> 2, c2 = (lane & 3) * 2;
#pragma unroll
    for (int mi = 0; mi < 2; mi++)
#pragma unroll
        for (int nj = 0; nj < 4; nj++) {
            int col = bn + wn * 32 + nj * 8 + c2;
            float2 bv = *(const float2*)(bias + col);
            int r0 = bm + wm * 32 + mi * 16 + g;
            if (r0 < M) {
                float2 o;
                o.x = fmaxf(acc[mi][nj][0] + bv.x, 0.f);
                o.y = fmaxf(acc[mi][nj][1] + bv.y, 0.f);
                *(float2*)(C + (size_t)r0 * N + col) = o;
            }
            int r1 = r0 + 8;
            if (r1 < M) {
                float2 o;
                o.x = fmaxf(acc[mi][nj][2] + bv.x, 0.f);
                o.y = fmaxf(acc[mi][nj][3] + bv.y, 0.f);
                *(float2*)(C + (size_t)r1 * N + col) = o;
            }
        }
}

// -------- layer 2: S = A@Bs + bias, T = A@Bt --------
__global__ void __launch_bounds__(256) k_mm_pair(
    const float* __restrict__ A,
    const __nv_bfloat16* __restrict__ Bsh, const __nv_bfloat16* __restrict__ Bsl,
    const __nv_bfloat16* __restrict__ Bth, const __nv_bfloat16* __restrict__ Btl,
    const float* __restrict__ bias, float* __restrict__ S, float* __restrict__ T,
    int M, int N, int K)
{
    extern __shared__ char smem[];
    const int OAH = 0, OAL = A_TILE_B;
    const int OB_BASE = 2 * A_TILE_B;
    uint32_t sb = smem_u32(smem);

    int tid = threadIdx.x, lane = tid & 31, wid = tid >> 5;
    int wm = wid & 3, wn = wid >> 2;
    int bm = blockIdx.y * 128, bn = blockIdx.x * 64;
    const int nch = K >> 5;

    int brow = tid >> 3, bseg = tid & 7;
    uint32_t bso = (uint32_t)(brow * 128 + ((bseg ^ (brow & 7)) << 4));
    const __nv_bfloat16* gB[4] = {Bsh, Bsl, Bth, Btl};

    float accS[2][4][4], accT[2][4][4];
#pragma unroll
    for (int i = 0; i < 2; i++)
#pragma unroll
        for (int j = 0; j < 4; j++)
#pragma unroll
            for (int q = 0; q < 4; q++) { accS[i][j][q] = 0.f; accT[i][j][q] = 0.f; }

    {
        size_t ge = (size_t)brow * N + bn + bseg * 8;
#pragma unroll
        for (int t = 0; t < 4; t++)
            CP_ASYNC16(sb + OB_BASE + t * B_TILE_B + bso, gB[t] + ge);
        CP_COMMIT();
    }

    for (int chunk = 0; chunk < nch; chunk++) {
        int k0 = chunk << 5;
        int obuf = OB_BASE + (chunk & 1) * 4 * B_TILE_B;

#pragma unroll
        for (int q = 0; q < 4; q++) {
            int slot = tid + q * 256;
            int row = slot >> 3, k4 = (slot & 7) * 4;
            int gr = bm + row;
            float4 v = {0.f, 0.f, 0.f, 0.f};
            if (gr < M) v = *(const float4*)(A + (size_t)gr * K + k0 + k4);
            uint32_t h[2], l[2];
            split4(v, h, l);
            int si = row * 20 + (k4 >> 1);
            ((uint32_t*)(smem + OAH))[si] = h[0];
            ((uint32_t*)(smem + OAH))[si + 1] = h[1];
            ((uint32_t*)(smem + OAL))[si] = l[0];
            ((uint32_t*)(smem + OAL))[si + 1] = l[1];
        }

        if (chunk + 1 < nch) {
            int nbuf = OB_BASE + ((chunk + 1) & 1) * 4 * B_TILE_B;
            size_t ge = (size_t)(((chunk + 1) << 5) + brow) * N + bn + bseg * 8;
#pragma unroll
            for (int t = 0; t < 4; t++)
                CP_ASYNC16(sb + nbuf + t * B_TILE_B + bso, gB[t] + ge);
            CP_COMMIT();
            CP_WAIT(1);
        } else {
            CP_WAIT(0);
        }
        __syncthreads();

#pragma unroll
        for (int kk = 0; kk < 2; kk++) {
            uint32_t fah[2][4], fal[2][4];
#pragma unroll
            for (int mi = 0; mi < 2; mi++) {
                uint32_t aoff = (uint32_t)((wm * 32 + mi * 16 + (lane & 15)) * 80 +
                                           (lane >> 4) * 16 + kk * 32);
                LDSM_X4(fah[mi][0], fah[mi][1], fah[mi][2], fah[mi][3], sb + OAH + aoff);
                LDSM_X4(fal[mi][0], fal[mi][1], fal[mi][2], fal[mi][3], sb + OAL + aoff);
            }
            uint32_t fbsh[4][2], fbsl[4][2], fbth[4][2], fbtl[4][2];
#pragma unroll
            for (int np = 0; np < 2; np++) {
                int r = kk * 16 + (lane & 7) + ((lane >> 3) & 1) * 8;
                int cu = wn * 4 + np * 2 + (lane >> 4);
                uint32_t boff = (uint32_t)(r * 128 + ((cu ^ (r & 7)) << 4));
                LDSM_X4T(fbsh[2 * np][0], fbsh[2 * np][1], fbsh[2 * np + 1][0], fbsh[2 * np + 1][1], sb + obuf + 0 * B_TILE_B + boff);
                LDSM_X4T(fbsl[2 * np][0], fbsl[2 * np][1], fbsl[2 * np + 1][0], fbsl[2 * np + 1][1], sb + obuf + 1 * B_TILE_B + boff);
                LDSM_X4T(fbth[2 * np][0], fbth[2 * np][1], fbth[2 * np + 1][0], fbth[2 * np + 1][1], sb + obuf + 2 * B_TILE_B + boff);
                LDSM_X4T(fbtl[2 * np][0], fbtl[2 * np][1], fbtl[2 * np + 1][0], fbtl[2 * np + 1][1], sb + obuf + 3 * B_TILE_B + boff);
            }
#pragma unroll
            for (int mi = 0; mi < 2; mi++)
#pragma unroll
                for (int nj = 0; nj < 4; nj++) {
                    MMA_BF16(accS[mi][nj], fah[mi], fbsh[nj]);
                    MMA_BF16(accS[mi][nj], fah[mi], fbsl[nj]);
                    MMA_BF16(accS[mi][nj], fal[mi], fbsh[nj]);
                    MMA_BF16(accT[mi][nj], fah[mi], fbth[nj]);
                    MMA_BF16(accT[mi][nj], fah[mi], fbtl[nj]);
                    MMA_BF16(accT[mi][nj], fal[mi], fbth[nj]);
                }
        }
        __syncthreads();
    }

    int g = lane >> 2, c2 = (lane & 3) * 2;
#pragma unroll
    for (int mi = 0; mi < 2; mi++)
#pragma unroll
        for (int nj = 0; nj < 4; nj++) {
            int col = bn + wn * 32 + nj * 8 + c2;
            float2 bv = *(const float2*)(bias + col);
            int r0 = bm + wm * 32 + mi * 16 + g;
            if (r0 < M) {
                float2 os = {accS[mi][nj][0] + bv.x, accS[mi][nj][1] + bv.y};
                *(float2*)(S + (size_t)r0 * N + col) = os;
                float2 ot = {accT[mi][nj][0], accT[mi][nj][1]};
                *(float2*)(T + (size_t)r0 * N + col) = ot;
            }
            int r1 = r0 + 8;
            if (r1 < M) {
                float2 os = {accS[mi][nj][2] + bv.x, accS[mi][nj][3] + bv.y};
                *(float2*)(S + (size_t)r1 * N + col) = os;
                float2 ot = {accT[mi][nj][2], accT[mi][nj][3]};
                *(float2*)(T + (size_t)r1 * N + col) = ot;
            }
        }
}

// ---------------- fused layer-2 aggregation + node scores: half-warp per node ----------------
__global__ void k_agg2_scores(const float* __restrict__ Wp) {
    int halves_per_blk = blockDim.x >> 4;
    int n = blockIdx.x * halves_per_blk + (threadIdx.x >> 4);
    if (n >= N_NODES) return;
    int lane = threadIdx.x & 15;
    int beg = g_rowptr[n], end = g_rowptr[n + 1];

    float4 aA0 = {0.f, 0.f, 0.f, 0.f}, aB0 = {0.f, 0.f, 0.f, 0.f};
    float4 aA1 = {0.f, 0.f, 0.f, 0.f}, aB1 = {0.f, 0.f, 0.f, 0.f};
    int j = beg;
    for (; j + 1 < end; j += 2) {
        int s0 = g_csr_src[j];
        int s1 = g_csr_src[j + 1];
        const float4* r0 = (const float4*)(g_t2 + (size_t)s0 * 128);
        const float4* r1 = (const float4*)(g_t2 + (size_t)s1 * 128);
        float4 vA0 = __ldg(&r0[lane]);
        float4 vB0 = __ldg(&r0[lane + 16]);
        float4 vA1 = __ldg(&r1[lane]);
        float4 vB1 = __ldg(&r1[lane + 16]);
        aA0.x += vA0.x; aA0.y += vA0.y; aA0.z += vA0.z; aA0.w += vA0.w;
        aB0.x += vB0.x; aB0.y += vB0.y; aB0.z += vB0.z; aB0.w += vB0.w;
        aA1.x += vA1.x; aA1.y += vA1.y; aA1.z += vA1.z; aA1.w += vA1.w;
        aB1.x += vB1.x; aB1.y += vB1.y; aB1.z += vB1.z; aB1.w += vB1.w;
    }
    if (j < end) {
        int s0 = g_csr_src[j];
        const float4* r0 = (const float4*)(g_t2 + (size_t)s0 * 128);
        float4 vA0 = __ldg(&r0[lane]);
        float4 vB0 = __ldg(&r0[lane + 16]);
        aA0.x += vA0.x; aA0.y += vA0.y; aA0.z += vA0.z; aA0.w += vA0.w;
        aB0.x += vB0.x; aB0.y += vB0.y; aB0.z += vB0.z; aB0.w += vB0.w;
    }
    aA0.x += aA1.x; aA0.y += aA1.y; aA0.z += aA1.z; aA0.w += aA1.w;
    aB0.x += aB1.x; aB0.y += aB1.y; aB0.z += aB1.z; aB0.w += aB1.w;

    int deg = end - beg;
    float inv = (deg > 0) ? 1.f / (float)deg : 0.f;
    const float4* srow = (const float4*)(g_s2 + (size_t)n * 128);
    float4 svA = srow[lane], svB = srow[lane + 16];
    float4 hA, hB;
    hA.x = svA.x + aA0.x * inv; hA.y = svA.y + aA0.y * inv;
    hA.z = svA.z + aA0.z * inv; hA.w = svA.w + aA0.w * inv;
    hB.x = svB.x + aB0.x * inv; hB.y = svB.y + aB0.y * inv;
    hB.z = svB.z + aB0.z * inv; hB.w = svB.w + aB0.w * inv;

    float4 waA = __ldg(&((const float4*)Wp)[lane]);
    float4 waB = __ldg(&((const float4*)Wp)[lane + 16]);
    float4 wbA = __ldg(&((const float4*)Wp)[lane + 32]);
    float4 wbB = __ldg(&((const float4*)Wp)[lane + 48]);
    float a = hA.x * waA.x + hA.y * waA.y + hA.z * waA.z + hA.w * waA.w
            + hB.x * waB.x + hB.y * waB.y + hB.z * waB.z + hB.w * waB.w;
    float b = hA.x * wbA.x + hA.y * wbA.y + hA.z * wbA.z + hA.w * wbA.w
            + hB.x * wbB.x + hB.y * wbB.y + hB.z * wbB.z + hB.w * wbB.w;
#pragma unroll
    for (int off = 8; off; off >>= 1) {
        a += __shfl_down_sync(0xFFFFFFFFu, a, off, 16);
        b += __shfl_down_sync(0xFFFFFFFFu, b, off, 16);
    }
    if (lane == 0) { g_sA[n] = a; g_sB[n] = b; }
}

__global__ void k_edge_scores(const int* __restrict__ psrc, const int* __restrict__ pdst,
                              const int* __restrict__ nsrc, const int* __restrict__ ndst,
                              const float* __restrict__ bp, float* __restrict__ out,
                              int EP, int EN) {
    int i = blockIdx.x * blockDim.x + threadIdx.x;
    float b = bp[0];
    if (i < EP) {
        out[i] = g_sA[psrc[i]] + g_sB[pdst[i]] + b;
    } else if (i < EP + EN) {
        int j = i - EP;
        out[i] = g_sA[nsrc[j]] + g_sB[ndst[j]] + b;
    }
}

// ---------------- launch ----------------
extern "C" void kernel_launch(void* const* d_in, const int* in_sizes, int n_in,
                              void* d_out, int out_size) {
    const float* x    = (const float*)d_in[0];
    const int* msrc   = (const int*)d_in[1];
    const int* mdst   = (const int*)d_in[2];
    const int* psrc   = (const int*)d_in[3];
    const int* pdst   = (const int*)d_in[4];
    const int* nsrc   = (const int*)d_in[5];
    const int* ndst   = (const int*)d_in[6];
    const float* W1s  = (const float*)d_in[7];
    const float* W1n  = (const float*)d_in[8];
    const float* b1   = (const float*)d_in[9];
    const float* W2s  = (const float*)d_in[10];
    const float* W2n  = (const float*)d_in[11];
    const float* b2   = (const float*)d_in[12];
    const float* Wp   = (const float*)d_in[13];
    const float* bp   = (const float*)d_in[14];
    float* out = (float*)d_out;

    int E  = in_sizes[1];
    int EP = in_sizes[3];
    int EN = in_sizes[5];

    float *p_neigh1, *p_h1, *p_s2, *p_t2;
    cudaGetSymbolAddress((void**)&p_neigh1, g_neigh1);
    cudaGetSymbolAddress((void**)&p_h1,     g_h1);
    cudaGetSymbolAddress((void**)&p_s2,     g_s2);
    cudaGetSymbolAddress((void**)&p_t2,     g_t2);

    __nv_bfloat16 *w1sh, *w1sl, *w1nh, *w1nl, *w2sh, *w2sl, *w2nh, *w2nl;
    cudaGetSymbolAddress((void**)&w1sh, g_w1s_h);
    cudaGetSymbolAddress((void**)&w1sl, g_w1s_l);
    cudaGetSymbolAddress((void**)&w1nh, g_w1n_h);
    cudaGetSymbolAddress((void**)&w1nl, g_w1n_l);
    cudaGetSymbolAddress((void**)&w2sh, g_w2s_h);
    cudaGetSymbolAddress((void**)&w2sl, g_w2s_l);
    cudaGetSymbolAddress((void**)&w2nh, g_w2n_h);
    cudaGetSymbolAddress((void**)&w2nl, g_w2n_l);

    const int SMEM_DUAL = 4 * A_TILE_B + 2 * 4 * B_TILE_B;  // 73728
    const int SMEM_PAIR = 2 * A_TILE_B + 2 * 4 * B_TILE_B;  // 53248
    cudaFuncSetAttribute(k_mm_dual, cudaFuncAttributeMaxDynamicSharedMemorySize, SMEM_DUAL);
    cudaFuncSetAttribute(k_mm_pair, cudaFuncAttributeMaxDynamicSharedMemorySize, SMEM_PAIR);

    // prep (cnt zero + weight split), then CSR build (2-phase scan)
    k_wprep_all<<<(4 * 32768 + 255) / 256, 256>>>(W1s, W1n, W2s, W2n);
    k_hist<<<(E + 255) / 256, 256>>>(mdst, E);
    k_scan1<<<NBLK_SCAN, 1024>>>();
    k_scan3<<<NBLK_SCAN, 1024>>>();
    k_fill<<<(E + 255) / 256, 256>>>(msrc, mdst, E);

    // layer 1
    k_agg128<<<(N_NODES + 15) / 16, 256>>>(x, p_neigh1);
    {
        dim3 grid(D_HID / 64, (N_NODES + 127) / 128);
        k_mm_dual<<<grid, 256, SMEM_DUAL>>>(x, p_neigh1, w1sh, w1sl, w1nh, w1nl,
                                            b1, p_h1, N_NODES, D_HID, D_IN);
    }
    // layer 2: project then aggregate
    {
        dim3 grid(D_OUT / 64, (N_NODES + 127) / 128);
        k_mm_pair<<<grid, 256, SMEM_PAIR>>>(p_h1, w2sh, w2sl, w2nh, w2nl,
                                            b2, p_s2, p_t2, N_NODES, D_OUT, D_HID);
    }
    k_agg2_scores<<<(N_NODES + 15) / 16, 256>>>(Wp);

    // edge scoring
    k_edge_scores<<<(EP + EN + 255) / 256, 256>>>(psrc, pdst, nsrc, ndst, bp, out, EP, EN);
}

// round 13
// speedup vs baseline: 1.4635x; 1.0458x over previous
#include <cuda_runtime.h>
#include <cuda_bf16.h>
#include <cstdint>

#define N_NODES 50000
#define MAX_E   800000
#define D_IN    128
#define D_HID   256
#define D_OUT   128
#define NBLK_SCAN ((N_NODES + 1023) / 1024)   // 49

// ---------------- scratch (static device globals; no allocation) ----------------
__device__ float g_neigh1[(size_t)N_NODES * D_IN];
__device__ float g_h1[(size_t)N_NODES * D_HID];
__device__ float g_s2[(size_t)N_NODES * D_OUT];
__device__ __nv_bfloat16 g_t2b[(size_t)N_NODES * D_OUT];   // t2 in bf16 (gather-only)
__device__ float g_sA[N_NODES];
__device__ float g_sB[N_NODES];
__device__ int   g_cnt[N_NODES];
__device__ int   g_rowptr[N_NODES + 1];
__device__ int   g_cursor[N_NODES];
__device__ int   g_csr_src[MAX_E];
__device__ int   g_blksum[64];

// pre-split bf16 weights, same (K,N) layout as the fp32 originals
__device__ __nv_bfloat16 g_w1s_h[D_IN * D_HID], g_w1s_l[D_IN * D_HID];
__device__ __nv_bfloat16 g_w1n_h[D_IN * D_HID], g_w1n_l[D_IN * D_HID];
__device__ __nv_bfloat16 g_w2s_h[D_HID * D_OUT], g_w2s_l[D_HID * D_OUT];
__device__ __nv_bfloat16 g_w2n_h[D_HID * D_OUT], g_w2n_l[D_HID * D_OUT];

// ---------------- helpers ----------------
__device__ __forceinline__ uint32_t smem_u32(const void* p) {
    uint32_t a;
    asm("{ .reg .u64 t; cvta.to.shared.u64 t, %1; cvt.u32.u64 %0, t; }" : "=r"(a) : "l"(p));
    return a;
}
__device__ __forceinline__ uint32_t bpack(__nv_bfloat16 a, __nv_bfloat16 b) {
    return (uint32_t)__bfloat16_as_ushort(a) | ((uint32_t)__bfloat16_as_ushort(b) << 16);
}
__device__ __forceinline__ void split4(float4 v, uint32_t* h, uint32_t* l) {
    __nv_bfloat16 hx = __float2bfloat16_rn(v.x);
    __nv_bfloat16 hy = __float2bfloat16_rn(v.y);
    __nv_bfloat16 hz = __float2bfloat16_rn(v.z);
    __nv_bfloat16 hw = __float2bfloat16_rn(v.w);
    h[0] = bpack(hx, hy);
    h[1] = bpack(hz, hw);
    __nv_bfloat16 lx = __float2bfloat16_rn(v.x - __bfloat162float(hx));
    __nv_bfloat16 ly = __float2bfloat16_rn(v.y - __bfloat162float(hy));
    __nv_bfloat16 lz = __float2bfloat16_rn(v.z - __bfloat162float(hz));
    __nv_bfloat16 lw = __float2bfloat16_rn(v.w - __bfloat162float(hw));
    l[0] = bpack(lx, ly);
    l[1] = bpack(lz, lw);
}
__device__ __forceinline__ void acc_bf16x8(float* acc, uint4 v) {
    float2 f;
    f = __bfloat1622float2(*(__nv_bfloat162*)&v.x); acc[0] += f.x; acc[1] += f.y;
    f = __bfloat1622float2(*(__nv_bfloat162*)&v.y); acc[2] += f.x; acc[3] += f.y;
    f = __bfloat1622float2(*(__nv_bfloat162*)&v.z); acc[4] += f.x; acc[5] += f.y;
    f = __bfloat1622float2(*(__nv_bfloat162*)&v.w); acc[6] += f.x; acc[7] += f.y;
}

#define LDSM_X4(r0, r1, r2, r3, addr) \
    asm volatile("ldmatrix.sync.aligned.m8n8.x4.shared.b16 {%0,%1,%2,%3}, [%4];" \
                 : "=r"(r0), "=r"(r1), "=r"(r2), "=r"(r3) : "r"(addr))
#define LDSM_X4T(r0, r1, r2, r3, addr) \
    asm volatile("ldmatrix.sync.aligned.m8n8.x4.trans.shared.b16 {%0,%1,%2,%3}, [%4];" \
                 : "=r"(r0), "=r"(r1), "=r"(r2), "=r"(r3) : "r"(addr))
#define MMA_BF16(c, a, b) \
    asm volatile("mma.sync.aligned.m16n8k16.row.col.f32.bf16.bf16.f32 " \
                 "{%0,%1,%2,%3}, {%4,%5,%6,%7}, {%8,%9}, {%0,%1,%2,%3};" \
                 : "+f"((c)[0]), "+f"((c)[1]), "+f"((c)[2]), "+f"((c)[3]) \
                 : "r"((a)[0]), "r"((a)[1]), "r"((a)[2]), "r"((a)[3]), \
                   "r"((b)[0]), "r"((b)[1]))
#define CP_ASYNC16(saddr, gptr) \
    asm volatile("cp.async.cg.shared.global [%0], [%1], 16;" :: "r"(saddr), "l"(gptr))
#define CP_COMMIT() asm volatile("cp.async.commit_group;")
#define CP_WAIT(n)  asm volatile("cp.async.wait_group %0;" :: "n"(n))

// ---------------- CSR build ----------------
__global__ void k_hist(const int* __restrict__ dst, int E) {
    int e = blockIdx.x * blockDim.x + threadIdx.x;
    if (e < E) atomicAdd(&g_cnt[dst[e]], 1);
}

__global__ void k_scan1() {
    __shared__ int sh[1024];
    int t = threadIdx.x;
    int idx = blockIdx.x * 1024 + t;
    sh[t] = (idx < N_NODES) ? g_cnt[idx] : 0;
    __syncthreads();
#pragma unroll
    for (int off = 512; off > 0; off >>= 1) {
        if (t < off) sh[t] += sh[t + off];
        __syncthreads();
    }
    if (t == 0) g_blksum[blockIdx.x] = sh[0];
}

// phase 2 (merged + shfl-scan): every block redundantly scans block sums,
// then warp-shuffle scans its 1024 counts -> rowptr/cursor.
__global__ void k_scan3() {
    __shared__ int bs[64];
    __shared__ int wscan[32];
    int t = threadIdx.x, lane = t & 31, w = t >> 5;

    if (w == 0) {
        int a0 = (lane < NBLK_SCAN) ? g_blksum[lane] : 0;
        int a1 = (lane + 32 < NBLK_SCAN) ? g_blksum[lane + 32] : 0;
#pragma unroll
        for (int off = 1; off < 32; off <<= 1) {
            int u = __shfl_up_sync(0xFFFFFFFFu, a0, off);
            if (lane >= off) a0 += u;
        }
        int tot0 = __shfl_sync(0xFFFFFFFFu, a0, 31);
#pragma unroll
        for (int off = 1; off < 32; off <<= 1) {
            int u = __shfl_up_sync(0xFFFFFFFFu, a1, off);
            if (lane >= off) a1 += u;
        }
        a1 += tot0;
        bs[lane] = a0;
        bs[lane + 32] = a1;
    }
    __syncthreads();
    int blk_off = (blockIdx.x == 0) ? 0 : bs[blockIdx.x - 1];
    if (blockIdx.x == 0 && t == 0) g_rowptr[N_NODES] = bs[NBLK_SCAN - 1];

    int idx = blockIdx.x * 1024 + t;
    int v = (idx < N_NODES) ? g_cnt[idx] : 0;
    int iv = v;
#pragma unroll
    for (int off = 1; off < 32; off <<= 1) {
        int u = __shfl_up_sync(0xFFFFFFFFu, iv, off);
        if (lane >= off) iv += u;
    }
    if (lane == 31) wscan[w] = iv;
    __syncthreads();
    if (w == 0) {
        int s = wscan[lane];
#pragma unroll
        for (int off = 1; off < 32; off <<= 1) {
            int u = __shfl_up_sync(0xFFFFFFFFu, s, off);
            if (lane >= off) s += u;
        }
        wscan[lane] = s;
    }
    __syncthreads();
    int warp_off = (w == 0) ? 0 : wscan[w - 1];
    if (idx < N_NODES) {
        int ex = iv - v + warp_off + blk_off;
        g_rowptr[idx] = ex;
        g_cursor[idx] = ex;
    }
}

__global__ void k_fill(const int* __restrict__ src, const int* __restrict__ dst, int E) {
    int e = blockIdx.x * blockDim.x + threadIdx.x;
    if (e < E) {
        int d = dst[e];
        int pos = atomicAdd(&g_cursor[d], 1);
        g_csr_src[pos] = src[e];
    }
}

// ---------------- layer-1 aggregation: half-warp per node, unrolled x2 ----------------
__global__ void k_agg128(const float* __restrict__ feat, float* __restrict__ out) {
    int halves_per_blk = blockDim.x >> 4;
    int n = blockIdx.x * halves_per_blk + (threadIdx.x >> 4);
    if (n >= N_NODES) return;
    int lane = threadIdx.x & 15;
    int beg = g_rowptr[n], end = g_rowptr[n + 1];

    float4 aA0 = {0.f, 0.f, 0.f, 0.f}, aB0 = {0.f, 0.f, 0.f, 0.f};
    float4 aA1 = {0.f, 0.f, 0.f, 0.f}, aB1 = {0.f, 0.f, 0.f, 0.f};
    int j = beg;
    for (; j + 1 < end; j += 2) {
        int s0 = g_csr_src[j];
        int s1 = g_csr_src[j + 1];
        const float4* r0 = (const float4*)(feat + (size_t)s0 * 128);
        const float4* r1 = (const float4*)(feat + (size_t)s1 * 128);
        float4 vA0 = __ldg(&r0[lane]);
        float4 vB0 = __ldg(&r0[lane + 16]);
        float4 vA1 = __ldg(&r1[lane]);
        float4 vB1 = __ldg(&r1[lane + 16]);
        aA0.x += vA0.x; aA0.y += vA0.y; aA0.z += vA0.z; aA0.w += vA0.w;
        aB0.x += vB0.x; aB0.y += vB0.y; aB0.z += vB0.z; aB0.w += vB0.w;
        aA1.x += vA1.x; aA1.y += vA1.y; aA1.z += vA1.z; aA1.w += vA1.w;
        aB1.x += vB1.x; aB1.y += vB1.y; aB1.z += vB1.z; aB1.w += vB1.w;
    }
    if (j < end) {
        int s0 = g_csr_src[j];
        const float4* r0 = (const float4*)(feat + (size_t)s0 * 128);
        float4 vA0 = __ldg(&r0[lane]);
        float4 vB0 = __ldg(&r0[lane + 16]);
        aA0.x += vA0.x; aA0.y += vA0.y; aA0.z += vA0.z; aA0.w += vA0.w;
        aB0.x += vB0.x; aB0.y += vB0.y; aB0.z += vB0.z; aB0.w += vB0.w;
    }
    aA0.x += aA1.x; aA0.y += aA1.y; aA0.z += aA1.z; aA0.w += aA1.w;
    aB0.x += aB1.x; aB0.y += aB1.y; aB0.z += aB1.z; aB0.w += aB1.w;
    int deg = end - beg;
    float inv = (deg > 0) ? 1.f / (float)deg : 0.f;
    float4* orow = (float4*)(out + (size_t)n * 128);
    float4 oA = {aA0.x * inv, aA0.y * inv, aA0.z * inv, aA0.w * inv};
    float4 oB = {aB0.x * inv, aB0.y * inv, aB0.z * inv, aB0.w * inv};
    orow[lane] = oA;
    orow[lane + 16] = oB;
}

// ---------------- weight split + cnt zeroing, one launch ----------------
__global__ void k_wprep_all(
    const float* __restrict__ W1s, const float* __restrict__ W1n,
    const float* __restrict__ W2s, const float* __restrict__ W2n)
{
    int i = blockIdx.x * blockDim.x + threadIdx.x;
    if (i < N_NODES) g_cnt[i] = 0;
    if (i >= 4 * 32768) return;
    int a = i >> 15, r = i & 32767;
    const float* W = (a == 0) ? W1s : (a == 1) ? W1n : (a == 2) ? W2s : W2n;
    __nv_bfloat16* hi = (a == 0) ? g_w1s_h : (a == 1) ? g_w1n_h : (a == 2) ? g_w2s_h : g_w2n_h;
    __nv_bfloat16* lo = (a == 0) ? g_w1s_l : (a == 1) ? g_w1n_l : (a == 2) ? g_w2s_l : g_w2n_l;
    float w = W[r];
    __nv_bfloat16 h = __float2bfloat16_rn(w);
    hi[r] = h;
    lo[r] = __float2bfloat16_rn(w - __bfloat162float(h));
}

// ================= bf16x3 mma.sync GEMMs: swizzled-B double-buffer =================
#define A_TILE_B 10240
#define B_TILE_B 4096

// -------- layer 1: C = relu(A1@B1 + A2@B2 + bias) --------
__global__ void __launch_bounds__(256) k_mm_dual(
    const float* __restrict__ A1, const float* __restrict__ A2,
    const __nv_bfloat16* __restrict__ B1h, const __nv_bfloat16* __restrict__ B1l,
    const __nv_bfloat16* __restrict__ B2h, const __nv_bfloat16* __restrict__ B2l,
    const float* __restrict__ bias, float* __restrict__ C,
    int M, int N, int K)
{
    extern __shared__ char smem[];
    const int OA1H = 0, OA1L = A_TILE_B, OA2H = 2 * A_TILE_B, OA2L = 3 * A_TILE_B;
    const int OB_BASE = 4 * A_TILE_B;
    uint32_t sb = smem_u32(smem);

    int tid = threadIdx.x, lane = tid & 31, wid = tid >> 5;
    int wm = wid & 3, wn = wid >> 2;
    int bm = blockIdx.y * 128, bn = blockIdx.x * 64;
    const int nch = K >> 5;

    int brow = tid >> 3, bseg = tid & 7;
    uint32_t bso = (uint32_t)(brow * 128 + ((bseg ^ (brow & 7)) << 4));
    const __nv_bfloat16* gB[4] = {B1h, B1l, B2h, B2l};

    float acc[2][4][4];
#pragma unroll
    for (int i = 0; i < 2; i++)
#pragma unroll
        for (int j = 0; j < 4; j++)
#pragma unroll
            for (int q = 0; q < 4; q++) acc[i][j][q] = 0.f;

    {
        size_t ge = (size_t)brow * N + bn + bseg * 8;
#pragma unroll
        for (int t = 0; t < 4; t++)
            CP_ASYNC16(sb + OB_BASE + t * B_TILE_B + bso, gB[t] + ge);
        CP_COMMIT();
    }

    for (int chunk = 0; chunk < nch; chunk++) {
        int k0 = chunk << 5;
        int obuf = OB_BASE + (chunk & 1) * 4 * B_TILE_B;

#pragma unroll
        for (int q = 0; q < 4; q++) {
            int slot = tid + q * 256;
            int row = slot >> 3, k4 = (slot & 7) * 4;
            int gr = bm + row;
            float4 v1 = {0.f, 0.f, 0.f, 0.f}, v2 = {0.f, 0.f, 0.f, 0.f};
            if (gr < M) {
                v1 = *(const float4*)(A1 + (size_t)gr * K + k0 + k4);
                v2 = *(const float4*)(A2 + (size_t)gr * K + k0 + k4);
            }
            uint32_t h[2], l[2];
            int si = row * 20 + (k4 >> 1);
            split4(v1, h, l);
            ((uint32_t*)(smem + OA1H))[si] = h[0];
            ((uint32_t*)(smem + OA1H))[si + 1] = h[1];
            ((uint32_t*)(smem + OA1L))[si] = l[0];
            ((uint32_t*)(smem + OA1L))[si + 1] = l[1];
            split4(v2, h, l);
            ((uint32_t*)(smem + OA2H))[si] = h[0];
            ((uint32_t*)(smem + OA2H))[si + 1] = h[1];
            ((uint32_t*)(smem + OA2L))[si] = l[0];
            ((uint32_t*)(smem + OA2L))[si + 1] = l[1];
        }

        if (chunk + 1 < nch) {
            int nbuf = OB_BASE + ((chunk + 1) & 1) * 4 * B_TILE_B;
            size_t ge = (size_t)(((chunk + 1) << 5) + brow) * N + bn + bseg * 8;
#pragma unroll
            for (int t = 0; t < 4; t++)
                CP_ASYNC16(sb + nbuf + t * B_TILE_B + bso, gB[t] + ge);
            CP_COMMIT();
            CP_WAIT(1);
        } else {
            CP_WAIT(0);
        }
        __syncthreads();

#pragma unroll
        for (int kk = 0; kk < 2; kk++) {
            uint32_t fa1h[2][4], fa1l[2][4], fa2h[2][4], fa2l[2][4];
#pragma unroll
            for (int mi = 0; mi < 2; mi++) {
                uint32_t aoff = (uint32_t)((wm * 32 + mi * 16 + (lane & 15)) * 80 +
                                           (lane >> 4) * 16 + kk * 32);
                LDSM_X4(fa1h[mi][0], fa1h[mi][1], fa1h[mi][2], fa1h[mi][3], sb + OA1H + aoff);
                LDSM_X4(fa1l[mi][0], fa1l[mi][1], fa1l[mi][2], fa1l[mi][3], sb + OA1L + aoff);
                LDSM_X4(fa2h[mi][0], fa2h[mi][1], fa2h[mi][2], fa2h[mi][3], sb + OA2H + aoff);
                LDSM_X4(fa2l[mi][0], fa2l[mi][1], fa2l[mi][2], fa2l[mi][3], sb + OA2L + aoff);
            }
            uint32_t fb1h[4][2], fb1l[4][2], fb2h[4][2], fb2l[4][2];
#pragma unroll
            for (int np = 0; np < 2; np++) {
                int r = kk * 16 + (lane & 7) + ((lane >> 3) & 1) * 8;
                int cu = wn * 4 + np * 2 + (lane >> 4);
                uint32_t boff = (uint32_t)(r * 128 + ((cu ^ (r & 7)) << 4));
                LDSM_X4T(fb1h[2 * np][0], fb1h[2 * np][1], fb1h[2 * np + 1][0], fb1h[2 * np + 1][1], sb + obuf + 0 * B_TILE_B + boff);
                LDSM_X4T(fb1l[2 * np][0], fb1l[2 * np][1], fb1l[2 * np + 1][0], fb1l[2 * np + 1][1], sb + obuf + 1 * B_TILE_B + boff);
                LDSM_X4T(fb2h[2 * np][0], fb2h[2 * np][1], fb2h[2 * np + 1][0], fb2h[2 * np + 1][1], sb + obuf + 2 * B_TILE_B + boff);
                LDSM_X4T(fb2l[2 * np][0], fb2l[2 * np][1], fb2l[2 * np + 1][0], fb2l[2 * np + 1][1], sb + obuf + 3 * B_TILE_B + boff);
            }
#pragma unroll
            for (int mi = 0; mi < 2; mi++)
#pragma unroll
                for (int nj = 0; nj < 4; nj++) {
                    MMA_BF16(acc[mi][nj], fa1h[mi], fb1h[nj]);
                    MMA_BF16(acc[mi][nj], fa1h[mi], fb1l[nj]);
                    MMA_BF16(acc[mi][nj], fa1l[mi], fb1h[nj]);
                    MMA_BF16(acc[mi][nj], fa2h[mi], fb2h[nj]);
                    MMA_BF16(acc[mi][nj], fa2h[mi], fb2l[nj]);
                    MMA_BF16(acc[mi][nj], fa2l[mi], fb2h[nj]);
                }
        }
        __syncthreads();
    }

    int g = lane >> 2, c2 = (lane & 3) * 2;
#pragma unroll
    for (int mi = 0; mi < 2; mi++)
#pragma unroll
        for (int nj = 0; nj < 4; nj++) {
            int col = bn + wn * 32 + nj * 8 + c2;
            float2 bv = *(const float2*)(bias + col);
            int r0 = bm + wm * 32 + mi * 16 + g;
            if (r0 < M) {
                float2 o;
                o.x = fmaxf(acc[mi][nj][0] + bv.x, 0.f);
                o.y = fmaxf(acc[mi][nj][1] + bv.y, 0.f);
                *(float2*)(C + (size_t)r0 * N + col) = o;
            }
            int r1 = r0 + 8;
            if (r1 < M) {
                float2 o;
                o.x = fmaxf(acc[mi][nj][2] + bv.x, 0.f);
                o.y = fmaxf(acc[mi][nj][3] + bv.y, 0.f);
                *(float2*)(C + (size_t)r1 * N + col) = o;
            }
        }
}

// -------- layer 2: S = A@Bs + bias (fp32), T = A@Bt (bf16) --------
__global__ void __launch_bounds__(256) k_mm_pair(
    const float* __restrict__ A,
    const __nv_bfloat16* __restrict__ Bsh, const __nv_bfloat16* __restrict__ Bsl,
    const __nv_bfloat16* __restrict__ Bth, const __nv_bfloat16* __restrict__ Btl,
    const float* __restrict__ bias, float* __restrict__ S, __nv_bfloat16* __restrict__ T,
    int M, int N, int K)
{
    extern __shared__ char smem[];
    const int OAH = 0, OAL = A_TILE_B;
    const int OB_BASE = 2 * A_TILE_B;
    uint32_t sb = smem_u32(smem);

    int tid = threadIdx.x, lane = tid & 31, wid = tid >> 5;
    int wm = wid & 3, wn = wid >> 2;
    int bm = blockIdx.y * 128, bn = blockIdx.x * 64;
    const int nch = K >> 5;

    int brow = tid >> 3, bseg = tid & 7;
    uint32_t bso = (uint32_t)(brow * 128 + ((bseg ^ (brow & 7)) << 4));
    const __nv_bfloat16* gB[4] = {Bsh, Bsl, Bth, Btl};

    float accS[2][4][4], accT[2][4][4];
#pragma unroll
    for (int i = 0; i < 2; i++)
#pragma unroll
        for (int j = 0; j < 4; j++)
#pragma unroll
            for (int q = 0; q < 4; q++) { accS[i][j][q] = 0.f; accT[i][j][q] = 0.f; }

    {
        size_t ge = (size_t)brow * N + bn + bseg * 8;
#pragma unroll
        for (int t = 0; t < 4; t++)
            CP_ASYNC16(sb + OB_BASE + t * B_TILE_B + bso, gB[t] + ge);
        CP_COMMIT();
    }

    for (int chunk = 0; chunk < nch; chunk++) {
        int k0 = chunk << 5;
        int obuf = OB_BASE + (chunk & 1) * 4 * B_TILE_B;

#pragma unroll
        for (int q = 0; q < 4; q++) {
            int slot = tid + q * 256;
            int row = slot >> 3, k4 = (slot & 7) * 4;
            int gr = bm + row;
            float4 v = {0.f, 0.f, 0.f, 0.f};
            if (gr < M) v = *(const float4*)(A + (size_t)gr * K + k0 + k4);
            uint32_t h[2], l[2];
            split4(v, h, l);
            int si = row * 20 + (k4 >> 1);
            ((uint32_t*)(smem + OAH))[si] = h[0];
            ((uint32_t*)(smem + OAH))[si + 1] = h[1];
            ((uint32_t*)(smem + OAL))[si] = l[0];
            ((uint32_t*)(smem + OAL))[si + 1] = l[1];
        }

        if (chunk + 1 < nch) {
            int nbuf = OB_BASE + ((chunk + 1) & 1) * 4 * B_TILE_B;
            size_t ge = (size_t)(((chunk + 1) << 5) + brow) * N + bn + bseg * 8;
#pragma unroll
            for (int t = 0; t < 4; t++)
                CP_ASYNC16(sb + nbuf + t * B_TILE_B + bso, gB[t] + ge);
            CP_COMMIT();
            CP_WAIT(1);
        } else {
            CP_WAIT(0);
        }
        __syncthreads();

#pragma unroll
        for (int kk = 0; kk < 2; kk++) {
            uint32_t fah[2][4], fal[2][4];
#pragma unroll
            for (int mi = 0; mi < 2; mi++) {
                uint32_t aoff = (uint32_t)((wm * 32 + mi * 16 + (lane & 15)) * 80 +
                                           (lane >> 4) * 16 + kk * 32);
                LDSM_X4(fah[mi][0], fah[mi][1], fah[mi][2], fah[mi][3], sb + OAH + aoff);
                LDSM_X4(fal[mi][0], fal[mi][1], fal[mi][2], fal[mi][3], sb + OAL + aoff);
            }
            uint32_t fbsh[4][2], fbsl[4][2], fbth[4][2], fbtl[4][2];
#pragma unroll
            for (int np = 0; np < 2; np++) {
                int r = kk * 16 + (lane & 7) + ((lane >> 3) & 1) * 8;
                int cu = wn * 4 + np * 2 + (lane >> 4);
                uint32_t boff = (uint32_t)(r * 128 + ((cu ^ (r & 7)) << 4));
                LDSM_X4T(fbsh[2 * np][0], fbsh[2 * np][1], fbsh[2 * np + 1][0], fbsh[2 * np + 1][1], sb + obuf + 0 * B_TILE_B + boff);
                LDSM_X4T(fbsl[2 * np][0], fbsl[2 * np][1], fbsl[2 * np + 1][0], fbsl[2 * np + 1][1], sb + obuf + 1 * B_TILE_B + boff);
                LDSM_X4T(fbth[2 * np][0], fbth[2 * np][1], fbth[2 * np + 1][0], fbth[2 * np + 1][1], sb + obuf + 2 * B_TILE_B + boff);
                LDSM_X4T(fbtl[2 * np][0], fbtl[2 * np][1], fbtl[2 * np + 1][0], fbtl[2 * np + 1][1], sb + obuf + 3 * B_TILE_B + boff);
            }
#pragma unroll
            for (int mi = 0; mi < 2; mi++)
#pragma unroll
                for (int nj = 0; nj < 4; nj++) {
                    MMA_BF16(accS[mi][nj], fah[mi], fbsh[nj]);
                    MMA_BF16(accS[mi][nj], fah[mi], fbsl[nj]);
                    MMA_BF16(accS[mi][nj], fal[mi], fbsh[nj]);
                    MMA_BF16(accT[mi][nj], fah[mi], fbth[nj]);
                    MMA_BF16(accT[mi][nj], fah[mi], fbtl[nj]);
                    MMA_BF16(accT[mi][nj], fal[mi], fbth[nj]);
                }
        }
        __syncthreads();
    }

    int g = lane >> 2, c2 = (lane & 3) * 2;
#pragma unroll
    for (int mi = 0; mi < 2; mi++)
#pragma unroll
        for (int nj = 0; nj < 4; nj++) {
            int col = bn + wn * 32 + nj * 8 + c2;
            float2 bv = *(const float2*)(bias + col);
            int r0 = bm + wm * 32 + mi * 16 + g;
            if (r0 < M) {
                float2 os = {accS[mi][nj][0] + bv.x, accS[mi][nj][1] + bv.y};
                *(float2*)(S + (size_t)r0 * N + col) = os;
                ((uint32_t*)T)[((size_t)r0 * N + col) >> 1] =
                    bpack(__float2bfloat16_rn(accT[mi][nj][0]), __float2bfloat16_rn(accT[mi][nj][1]));
            }
            int r1 = r0 + 8;
            if (r1 < M) {
                float2 os = {accS[mi][nj][2] + bv.x, accS[mi][nj][3] + bv.y};
                *(float2*)(S + (size_t)r1 * N + col) = os;
                ((uint32_t*)T)[((size_t)r1 * N + col) >> 1] =
                    bpack(__float2bfloat16_rn(accT[mi][nj][2]), __float2bfloat16_rn(accT[mi][nj][3]));
            }
        }
}

// ---------------- fused layer-2 aggregation + node scores: half-warp, bf16 t2 ----------------
__global__ void k_agg2_scores(const float* __restrict__ Wp) {
    int halves_per_blk = blockDim.x >> 4;
    int n = blockIdx.x * halves_per_blk + (threadIdx.x >> 4);
    if (n >= N_NODES) return;
    int lane = threadIdx.x & 15;
    int beg = g_rowptr[n], end = g_rowptr[n + 1];

    float a0[8] = {0.f, 0.f, 0.f, 0.f, 0.f, 0.f, 0.f, 0.f};
    float a1[8] = {0.f, 0.f, 0.f, 0.f, 0.f, 0.f, 0.f, 0.f};
    int j = beg;
    for (; j + 1 < end; j += 2) {
        int s0 = g_csr_src[j];
        int s1 = g_csr_src[j + 1];
        uint4 v0 = __ldg(&((const uint4*)(g_t2b + (size_t)s0 * 128))[lane]);
        uint4 v1 = __ldg(&((const uint4*)(g_t2b + (size_t)s1 * 128))[lane]);
        acc_bf16x8(a0, v0);
        acc_bf16x8(a1, v1);
    }
    if (j < end) {
        int s0 = g_csr_src[j];
        uint4 v0 = __ldg(&((const uint4*)(g_t2b + (size_t)s0 * 128))[lane]);
        acc_bf16x8(a0, v0);
    }
#pragma unroll
    for (int q = 0; q < 8; q++) a0[q] += a1[q];

    int deg = end - beg;
    float inv = (deg > 0) ? 1.f / (float)deg : 0.f;
    const float4* srow = (const float4*)(g_s2 + (size_t)n * 128);
    float4 sv0 = srow[lane * 2], sv1 = srow[lane * 2 + 1];
    float h[8];
    h[0] = sv0.x + a0[0] * inv; h[1] = sv0.y + a0[1] * inv;
    h[2] = sv0.z + a0[2] * inv; h[3] = sv0.w + a0[3] * inv;
    h[4] = sv1.x + a0[4] * inv; h[5] = sv1.y + a0[5] * inv;
    h[6] = sv1.z + a0[6] * inv; h[7] = sv1.w + a0[7] * inv;

    const float4* wp4 = (const float4*)Wp;
    float4 wa0 = __ldg(&wp4[lane * 2]);
    float4 wa1 = __ldg(&wp4[lane * 2 + 1]);
    float4 wb0 = __ldg(&wp4[32 + lane * 2]);
    float4 wb1 = __ldg(&wp4[32 + lane * 2 + 1]);
    float a = h[0] * wa0.x + h[1] * wa0.y + h[2] * wa0.z + h[3] * wa0.w
            + h[4] * wa1.x + h[5] * wa1.y + h[6] * wa1.z + h[7] * wa1.w;
    float b = h[0] * wb0.x + h[1] * wb0.y + h[2] * wb0.z + h[3] * wb0.w
            + h[4] * wb1.x + h[5] * wb1.y + h[6] * wb1.z + h[7] * wb1.w;
#pragma unroll
    for (int off = 8; off; off >>= 1) {
        a += __shfl_down_sync(0xFFFFFFFFu, a, off, 16);
        b += __shfl_down_sync(0xFFFFFFFFu, b, off, 16);
    }
    if (lane == 0) { g_sA[n] = a; g_sB[n] = b; }
}

__global__ void k_edge_scores(const int* __restrict__ psrc, const int* __restrict__ pdst,
                              const int* __restrict__ nsrc, const int* __restrict__ ndst,
                              const float* __restrict__ bp, float* __restrict__ out,
                              int EP, int EN) {
    int i = blockIdx.x * blockDim.x + threadIdx.x;
    float b = bp[0];
    if (i < EP) {
        out[i] = g_sA[psrc[i]] + g_sB[pdst[i]] + b;
    } else if (i < EP + EN) {
        int j = i - EP;
        out[i] = g_sA[nsrc[j]] + g_sB[ndst[j]] + b;
    }
}

// ---------------- launch ----------------
extern "C" void kernel_launch(void* const* d_in, const int* in_sizes, int n_in,
                              void* d_out, int out_size) {
    const float* x    = (const float*)d_in[0];
    const int* msrc   = (const int*)d_in[1];
    const int* mdst   = (const int*)d_in[2];
    const int* psrc   = (const int*)d_in[3];
    const int* pdst   = (const int*)d_in[4];
    const int* nsrc   = (const int*)d_in[5];
    const int* ndst   = (const int*)d_in[6];
    const float* W1s  = (const float*)d_in[7];
    const float* W1n  = (const float*)d_in[8];
    const float* b1   = (const float*)d_in[9];
    const float* W2s  = (const float*)d_in[10];
    const float* W2n  = (const float*)d_in[11];
    const float* b2   = (const float*)d_in[12];
    const float* Wp   = (const float*)d_in[13];
    const float* bp   = (const float*)d_in[14];
    float* out = (float*)d_out;

    int E  = in_sizes[1];
    int EP = in_sizes[3];
    int EN = in_sizes[5];

    float *p_neigh1, *p_h1, *p_s2;
    __nv_bfloat16* p_t2b;
    cudaGetSymbolAddress((void**)&p_neigh1, g_neigh1);
    cudaGetSymbolAddress((void**)&p_h1,     g_h1);
    cudaGetSymbolAddress((void**)&p_s2,     g_s2);
    cudaGetSymbolAddress((void**)&p_t2b,    g_t2b);

    __nv_bfloat16 *w1sh, *w1sl, *w1nh, *w1nl, *w2sh, *w2sl, *w2nh, *w2nl;
    cudaGetSymbolAddress((void**)&w1sh, g_w1s_h);
    cudaGetSymbolAddress((void**)&w1sl, g_w1s_l);
    cudaGetSymbolAddress((void**)&w1nh, g_w1n_h);
    cudaGetSymbolAddress((void**)&w1nl, g_w1n_l);
    cudaGetSymbolAddress((void**)&w2sh, g_w2s_h);
    cudaGetSymbolAddress((void**)&w2sl, g_w2s_l);
    cudaGetSymbolAddress((void**)&w2nh, g_w2n_h);
    cudaGetSymbolAddress((void**)&w2nl, g_w2n_l);

    const int SMEM_DUAL = 4 * A_TILE_B + 2 * 4 * B_TILE_B;  // 73728
    const int SMEM_PAIR = 2 * A_TILE_B + 2 * 4 * B_TILE_B;  // 53248
    cudaFuncSetAttribute(k_mm_dual, cudaFuncAttributeMaxDynamicSharedMemorySize, SMEM_DUAL);
    cudaFuncSetAttribute(k_mm_pair, cudaFuncAttributeMaxDynamicSharedMemorySize, SMEM_PAIR);

    // prep (cnt zero + weight split), then CSR build (2-phase scan)
    k_wprep_all<<<(4 * 32768 + 255) / 256, 256>>>(W1s, W1n, W2s, W2n);
    k_hist<<<(E + 255) / 256, 256>>>(mdst, E);
    k_scan1<<<NBLK_SCAN, 1024>>>();
    k_scan3<<<NBLK_SCAN, 1024>>>();
    k_fill<<<(E + 255) / 256, 256>>>(msrc, mdst, E);

    // layer 1
    k_agg128<<<(N_NODES + 15) / 16, 256>>>(x, p_neigh1);
    {
        dim3 grid(D_HID / 64, (N_NODES + 127) / 128);
        k_mm_dual<<<grid, 256, SMEM_DUAL>>>(x, p_neigh1, w1sh, w1sl, w1nh, w1nl,
                                            b1, p_h1, N_NODES, D_HID, D_IN);
    }
    // layer 2: project then aggregate (t2 stored bf16)
    {
        dim3 grid(D_OUT / 64, (N_NODES + 127) / 128);
        k_mm_pair<<<grid, 256, SMEM_PAIR>>>(p_h1, w2sh, w2sl, w2nh, w2nl,
                                            b2, p_s2, p_t2b, N_NODES, D_OUT, D_HID);
    }
    k_agg2_scores<<<(N_NODES + 15) / 16, 256>>>(Wp);

    // edge scoring
    k_edge_scores<<<(EP + EN + 255) / 256, 256>>>(psrc, pdst, nsrc, ndst, bp, out, EP, EN);
}